// round 1
// baseline (speedup 1.0000x reference)
#include <cuda_runtime.h>

#define NM 256          // N_MODES
#define NL 4            // N_LAYERS
#define TILE_B 64
#define KC 32
#define HS_STRIDE 260   // padded to kill decoder bank conflicts (mult of 4 for float4)

// Per-layer folded matrices: A[l][j][n] = conv kernel shifted + lw diagonal.
__device__ float g_A[NL][NM][NM];   // 1 MB, L2-resident during main kernel
__device__ float g_k[NL][NM];

// ---------------------------------------------------------------------------
// build_mats: k_l = irfft(fw_l); fill A_l and keep k_l for the x-bias term.
// grid (NL, 8): blockIdx.y covers 32 j-rows each; k recomputed redundantly (cheap).
// ---------------------------------------------------------------------------
__global__ void build_mats(const float* __restrict__ fw,
                           const float* __restrict__ lw) {
    const int l = blockIdx.x;
    const int n = threadIdx.x;
    __shared__ float ks[NM];

    const float* fwl = fw + l * (NM / 2 + 1);
    // irfft of a real spectrum: k[n] = (fw0 + 2*sum fw_m cos(2pi m n/256) + fw128*(-1)^n)/256
    float s = fwl[0];
    #pragma unroll 4
    for (int m = 1; m < NM / 2; ++m)
        s += 2.0f * fwl[m] * cospif((float)(m * n) * (1.0f / 128.0f)); // exact arg: mn/128
    s += fwl[NM / 2] * ((n & 1) ? -1.0f : 1.0f);
    const float kv = s * (1.0f / 256.0f);
    ks[n] = kv;
    if (blockIdx.y == 0) g_k[l][n] = kv;
    __syncthreads();

    const float lwn = lw[l * NM + n];
    const int j0 = blockIdx.y * (NM / 8);
    for (int j = j0; j < j0 + NM / 8; ++j) {
        float v = (j < NM - 3) ? ks[(n - j - 3) & (NM - 1)] : 0.0f;
        if (j == n) v += lwn;
        g_A[l][j][n] = v;   // coalesced over n
    }
}

// ---------------------------------------------------------------------------
// Fused chain kernel. One CTA = 64 rows, h lives in SMEM across all stages.
// Thread (tx,ty) of 16x16 owns rows ty*4+i (i<4) and col groups 4*(tx+16*j4).
// ---------------------------------------------------------------------------
__device__ __forceinline__ void mma_chunk(const float* __restrict__ hs,
                                          const float* __restrict__ as_,
                                          int kb, int tx, int ty,
                                          float4 acc[4][4]) {
    #pragma unroll
    for (int k4 = 0; k4 < KC / 4; ++k4) {
        float4 av[4];
        #pragma unroll
        for (int i = 0; i < 4; ++i)
            av[i] = *(const float4*)(hs + (ty * 4 + i) * HS_STRIDE + kb + 4 * k4);
        #pragma unroll
        for (int kk = 0; kk < 4; ++kk) {
            #pragma unroll
            for (int j4 = 0; j4 < 4; ++j4) {
                float4 b = *(const float4*)(as_ + (4 * k4 + kk) * NM + 4 * (tx + 16 * j4));
                #pragma unroll
                for (int i = 0; i < 4; ++i) {
                    float a = (kk == 0) ? av[i].x : (kk == 1) ? av[i].y
                              : (kk == 2) ? av[i].z : av[i].w;
                    acc[i][j4].x += a * b.x;
                    acc[i][j4].y += a * b.y;
                    acc[i][j4].z += a * b.z;
                    acc[i][j4].w += a * b.w;
                }
            }
        }
    }
}

__global__ __launch_bounds__(256, 2)
void fno_main(const float* __restrict__ mu, const float* __restrict__ x,
              const float* __restrict__ W1, const float* __restrict__ b1,
              const float* __restrict__ W2, const float* __restrict__ b2,
              float* __restrict__ out) {
    extern __shared__ float sm[];
    float* hs  = sm;                          // TILE_B * HS_STRIDE
    float* as_ = hs + TILE_B * HS_STRIDE;     // KC * NM
    float* ksh = as_ + KC * NM;               // NM
    float* bsh = ksh + NM;                    // NM (b1 / W2 staging)
    float* xsh = bsh + NM;                    // TILE_B * 4

    const int tid = threadIdx.x;
    const int tx = tid & 15, ty = tid >> 4;
    const long long row0 = (long long)blockIdx.x * TILE_B;

    // stage mu tile into hs[:, 0:64]
    {
        const float4* mu4 = (const float4*)(mu + row0 * 64);
        for (int i = tid; i < TILE_B * 16; i += 256) {
            int r = i >> 4, c = i & 15;
            *(float4*)(hs + r * HS_STRIDE + 4 * c) = mu4[r * 16 + c];
        }
    }
    if (tid < TILE_B * 3)
        xsh[(tid / 3) * 4 + (tid % 3)] = x[(row0 + tid / 3) * 3 + (tid % 3)];
    bsh[tid] = b1[tid];
    __syncthreads();

    float4 acc[4][4];

    // ---- encoder: h = relu(mu @ W1 + b1), K = 64
    {
        #pragma unroll
        for (int j4 = 0; j4 < 4; ++j4) {
            float4 bi = *(const float4*)(bsh + 4 * (tx + 16 * j4));
            #pragma unroll
            for (int i = 0; i < 4; ++i) acc[i][j4] = bi;
        }
        for (int kb = 0; kb < 64; kb += KC) {
            const float4* w4 = (const float4*)(W1 + kb * NM);
            float4* as4 = (float4*)as_;
            for (int i = tid; i < KC * (NM / 4); i += 256) as4[i] = w4[i];
            __syncthreads();
            mma_chunk(hs, as_, kb, tx, ty, acc);
            __syncthreads();
        }
        #pragma unroll
        for (int i = 0; i < 4; ++i)
            #pragma unroll
            for (int j4 = 0; j4 < 4; ++j4) {
                float4 v = acc[i][j4];
                v.x = fmaxf(v.x, 0.f); v.y = fmaxf(v.y, 0.f);
                v.z = fmaxf(v.z, 0.f); v.w = fmaxf(v.w, 0.f);
                *(float4*)(hs + (ty * 4 + i) * HS_STRIDE + 4 * (tx + 16 * j4)) = v;
            }
        __syncthreads();
    }

    // ---- 4 Fourier layers: h = relu(h @ A_l + x @ Cx_l)
    for (int l = 0; l < NL; ++l) {
        ksh[tid] = g_k[l][tid];
        __syncthreads();

        // init acc with x-bias: bias[n] = x0*k[n] + x1*k[n-1] + x2*k[n-2] (circular)
        #pragma unroll
        for (int j4 = 0; j4 < 4; ++j4) {
            const int c = 4 * (tx + 16 * j4);
            float kv[6];
            #pragma unroll
            for (int m = 0; m < 6; ++m) kv[m] = ksh[(c + m - 2) & (NM - 1)];
            #pragma unroll
            for (int i = 0; i < 4; ++i) {
                const float* xr = xsh + (ty * 4 + i) * 4;
                float4 v;
                v.x = xr[0] * kv[2] + xr[1] * kv[1] + xr[2] * kv[0];
                v.y = xr[0] * kv[3] + xr[1] * kv[2] + xr[2] * kv[1];
                v.z = xr[0] * kv[4] + xr[1] * kv[3] + xr[2] * kv[2];
                v.w = xr[0] * kv[5] + xr[1] * kv[4] + xr[2] * kv[3];
                acc[i][j4] = v;
            }
        }

        for (int kb = 0; kb < NM; kb += KC) {
            const float4* a4 = (const float4*)(&g_A[l][kb][0]);
            float4* as4 = (float4*)as_;
            for (int i = tid; i < KC * (NM / 4); i += 256) as4[i] = a4[i];
            __syncthreads();
            mma_chunk(hs, as_, kb, tx, ty, acc);
            __syncthreads();
        }

        #pragma unroll
        for (int i = 0; i < 4; ++i)
            #pragma unroll
            for (int j4 = 0; j4 < 4; ++j4) {
                float4 v = acc[i][j4];
                v.x = fmaxf(v.x, 0.f); v.y = fmaxf(v.y, 0.f);
                v.z = fmaxf(v.z, 0.f); v.w = fmaxf(v.w, 0.f);
                *(float4*)(hs + (ty * 4 + i) * HS_STRIDE + 4 * (tx + 16 * j4)) = v;
            }
        __syncthreads();
    }

    // ---- decoder: out = h @ W2 + b2 (4 threads per row, interleaved cols)
    bsh[tid] = W2[tid];
    __syncthreads();
    {
        const int r = tid >> 2, part = tid & 3;
        const float* hr = hs + r * HS_STRIDE;
        float s = 0.f;
        #pragma unroll 8
        for (int i = 0; i < 64; ++i) {
            int c = part + 4 * i;
            s += hr[c] * bsh[c];
        }
        s += __shfl_xor_sync(0xffffffffu, s, 1);
        s += __shfl_xor_sync(0xffffffffu, s, 2);
        if (part == 0) out[row0 + r] = s + b2[0];
    }
}

// ---------------------------------------------------------------------------
extern "C" void kernel_launch(void* const* d_in, const int* in_sizes, int n_in,
                              void* d_out, int out_size) {
    const float* mu = (const float*)d_in[0];
    const float* x  = (const float*)d_in[1];
    const float* W1 = (const float*)d_in[2];
    const float* b1 = (const float*)d_in[3];
    const float* fw = (const float*)d_in[4];
    const float* lw = (const float*)d_in[5];
    const float* W2 = (const float*)d_in[6];
    const float* b2 = (const float*)d_in[7];
    float* out = (float*)d_out;

    const int B = in_sizes[0] / 64;   // mu is [B, 64]

    build_mats<<<dim3(NL, 8), NM>>>(fw, lw);

    const int smem_bytes =
        (TILE_B * HS_STRIDE + KC * NM + NM + NM + TILE_B * 4) * (int)sizeof(float);
    cudaFuncSetAttribute(fno_main, cudaFuncAttributeMaxDynamicSharedMemorySize,
                         smem_bytes);
    fno_main<<<B / TILE_B, 256, smem_bytes>>>(mu, x, W1, b1, W2, b2, out);
}

// round 2
// speedup vs baseline: 1.0001x; 1.0001x over previous
#include <cuda_runtime.h>

#define NM 256          // N_MODES
#define NL 4            // N_LAYERS
#define TILE_B 64
#define KC 32
#define HS_STRIDE 260   // padded to kill decoder bank conflicts (mult of 4 for float4)

// Per-layer folded matrices: A[l][j][n] = conv kernel shifted + lw diagonal.
__device__ float g_A[NL][NM][NM];   // 1 MB, L2-resident during main kernel
__device__ float g_k[NL][NM];

// ---------------------------------------------------------------------------
// build_mats: k_l = irfft(fw_l); fill A_l and keep k_l for the x-bias term.
// grid (NL, 8): blockIdx.y covers 32 j-rows each; k recomputed redundantly (cheap).
// ---------------------------------------------------------------------------
__global__ void build_mats(const float* __restrict__ fw,
                           const float* __restrict__ lw) {
    const int l = blockIdx.x;
    const int n = threadIdx.x;
    __shared__ float ks[NM];

    const float* fwl = fw + l * (NM / 2 + 1);
    // irfft of a real spectrum: k[n] = (fw0 + 2*sum fw_m cos(2pi m n/256) + fw128*(-1)^n)/256
    float s = fwl[0];
    #pragma unroll 4
    for (int m = 1; m < NM / 2; ++m)
        s += 2.0f * fwl[m] * cospif((float)(m * n) * (1.0f / 128.0f)); // exact arg: mn/128
    s += fwl[NM / 2] * ((n & 1) ? -1.0f : 1.0f);
    const float kv = s * (1.0f / 256.0f);
    ks[n] = kv;
    if (blockIdx.y == 0) g_k[l][n] = kv;
    __syncthreads();

    const float lwn = lw[l * NM + n];
    const int j0 = blockIdx.y * (NM / 8);
    for (int j = j0; j < j0 + NM / 8; ++j) {
        float v = (j < NM - 3) ? ks[(n - j - 3) & (NM - 1)] : 0.0f;
        if (j == n) v += lwn;
        g_A[l][j][n] = v;   // coalesced over n
    }
}

// ---------------------------------------------------------------------------
// Fused chain kernel. One CTA = 64 rows, h lives in SMEM across all stages.
// Thread (tx,ty) of 16x16 owns rows ty*4+i (i<4) and col groups 4*(tx+16*j4).
// ---------------------------------------------------------------------------
__device__ __forceinline__ void mma_chunk(const float* __restrict__ hs,
                                          const float* __restrict__ as_,
                                          int kb, int tx, int ty,
                                          float4 acc[4][4]) {
    #pragma unroll
    for (int k4 = 0; k4 < KC / 4; ++k4) {
        float4 av[4];
        #pragma unroll
        for (int i = 0; i < 4; ++i)
            av[i] = *(const float4*)(hs + (ty * 4 + i) * HS_STRIDE + kb + 4 * k4);
        #pragma unroll
        for (int kk = 0; kk < 4; ++kk) {
            #pragma unroll
            for (int j4 = 0; j4 < 4; ++j4) {
                float4 b = *(const float4*)(as_ + (4 * k4 + kk) * NM + 4 * (tx + 16 * j4));
                #pragma unroll
                for (int i = 0; i < 4; ++i) {
                    float a = (kk == 0) ? av[i].x : (kk == 1) ? av[i].y
                              : (kk == 2) ? av[i].z : av[i].w;
                    acc[i][j4].x += a * b.x;
                    acc[i][j4].y += a * b.y;
                    acc[i][j4].z += a * b.z;
                    acc[i][j4].w += a * b.w;
                }
            }
        }
    }
}

__global__ __launch_bounds__(256, 2)
void fno_main(const float* __restrict__ mu, const float* __restrict__ x,
              const float* __restrict__ W1, const float* __restrict__ b1,
              const float* __restrict__ W2, const float* __restrict__ b2,
              float* __restrict__ out) {
    extern __shared__ float sm[];
    float* hs  = sm;                          // TILE_B * HS_STRIDE
    float* as_ = hs + TILE_B * HS_STRIDE;     // KC * NM
    float* ksh = as_ + KC * NM;               // NM
    float* bsh = ksh + NM;                    // NM (b1 / W2 staging)
    float* xsh = bsh + NM;                    // TILE_B * 4

    const int tid = threadIdx.x;
    const int tx = tid & 15, ty = tid >> 4;
    const long long row0 = (long long)blockIdx.x * TILE_B;

    // stage mu tile into hs[:, 0:64]
    {
        const float4* mu4 = (const float4*)(mu + row0 * 64);
        for (int i = tid; i < TILE_B * 16; i += 256) {
            int r = i >> 4, c = i & 15;
            *(float4*)(hs + r * HS_STRIDE + 4 * c) = mu4[r * 16 + c];
        }
    }
    if (tid < TILE_B * 3)
        xsh[(tid / 3) * 4 + (tid % 3)] = x[(row0 + tid / 3) * 3 + (tid % 3)];
    bsh[tid] = b1[tid];
    __syncthreads();

    float4 acc[4][4];

    // ---- encoder: h = relu(mu @ W1 + b1), K = 64
    {
        #pragma unroll
        for (int j4 = 0; j4 < 4; ++j4) {
            float4 bi = *(const float4*)(bsh + 4 * (tx + 16 * j4));
            #pragma unroll
            for (int i = 0; i < 4; ++i) acc[i][j4] = bi;
        }
        for (int kb = 0; kb < 64; kb += KC) {
            const float4* w4 = (const float4*)(W1 + kb * NM);
            float4* as4 = (float4*)as_;
            for (int i = tid; i < KC * (NM / 4); i += 256) as4[i] = w4[i];
            __syncthreads();
            mma_chunk(hs, as_, kb, tx, ty, acc);
            __syncthreads();
        }
        #pragma unroll
        for (int i = 0; i < 4; ++i)
            #pragma unroll
            for (int j4 = 0; j4 < 4; ++j4) {
                float4 v = acc[i][j4];
                v.x = fmaxf(v.x, 0.f); v.y = fmaxf(v.y, 0.f);
                v.z = fmaxf(v.z, 0.f); v.w = fmaxf(v.w, 0.f);
                *(float4*)(hs + (ty * 4 + i) * HS_STRIDE + 4 * (tx + 16 * j4)) = v;
            }
        __syncthreads();
    }

    // ---- 4 Fourier layers: h = relu(h @ A_l + x @ Cx_l)
    for (int l = 0; l < NL; ++l) {
        ksh[tid] = g_k[l][tid];
        __syncthreads();

        // init acc with x-bias: bias[n] = x0*k[n] + x1*k[n-1] + x2*k[n-2] (circular)
        #pragma unroll
        for (int j4 = 0; j4 < 4; ++j4) {
            const int c = 4 * (tx + 16 * j4);
            float kv[6];
            #pragma unroll
            for (int m = 0; m < 6; ++m) kv[m] = ksh[(c + m - 2) & (NM - 1)];
            #pragma unroll
            for (int i = 0; i < 4; ++i) {
                const float* xr = xsh + (ty * 4 + i) * 4;
                float4 v;
                v.x = xr[0] * kv[2] + xr[1] * kv[1] + xr[2] * kv[0];
                v.y = xr[0] * kv[3] + xr[1] * kv[2] + xr[2] * kv[1];
                v.z = xr[0] * kv[4] + xr[1] * kv[3] + xr[2] * kv[2];
                v.w = xr[0] * kv[5] + xr[1] * kv[4] + xr[2] * kv[3];
                acc[i][j4] = v;
            }
        }

        for (int kb = 0; kb < NM; kb += KC) {
            const float4* a4 = (const float4*)(&g_A[l][kb][0]);
            float4* as4 = (float4*)as_;
            for (int i = tid; i < KC * (NM / 4); i += 256) as4[i] = a4[i];
            __syncthreads();
            mma_chunk(hs, as_, kb, tx, ty, acc);
            __syncthreads();
        }

        #pragma unroll
        for (int i = 0; i < 4; ++i)
            #pragma unroll
            for (int j4 = 0; j4 < 4; ++j4) {
                float4 v = acc[i][j4];
                v.x = fmaxf(v.x, 0.f); v.y = fmaxf(v.y, 0.f);
                v.z = fmaxf(v.z, 0.f); v.w = fmaxf(v.w, 0.f);
                *(float4*)(hs + (ty * 4 + i) * HS_STRIDE + 4 * (tx + 16 * j4)) = v;
            }
        __syncthreads();
    }

    // ---- decoder: out = h @ W2 + b2 (4 threads per row, interleaved cols)
    bsh[tid] = W2[tid];
    __syncthreads();
    {
        const int r = tid >> 2, part = tid & 3;
        const float* hr = hs + r * HS_STRIDE;
        float s = 0.f;
        #pragma unroll 8
        for (int i = 0; i < 64; ++i) {
            int c = part + 4 * i;
            s += hr[c] * bsh[c];
        }
        s += __shfl_xor_sync(0xffffffffu, s, 1);
        s += __shfl_xor_sync(0xffffffffu, s, 2);
        if (part == 0) out[row0 + r] = s + b2[0];
    }
}

// ---------------------------------------------------------------------------
extern "C" void kernel_launch(void* const* d_in, const int* in_sizes, int n_in,
                              void* d_out, int out_size) {
    const float* mu = (const float*)d_in[0];
    const float* x  = (const float*)d_in[1];
    const float* W1 = (const float*)d_in[2];
    const float* b1 = (const float*)d_in[3];
    const float* fw = (const float*)d_in[4];
    const float* lw = (const float*)d_in[5];
    const float* W2 = (const float*)d_in[6];
    const float* b2 = (const float*)d_in[7];
    float* out = (float*)d_out;

    const int B = in_sizes[0] / 64;   // mu is [B, 64]

    build_mats<<<dim3(NL, 8), NM>>>(fw, lw);

    const int smem_bytes =
        (TILE_B * HS_STRIDE + KC * NM + NM + NM + TILE_B * 4) * (int)sizeof(float);
    cudaFuncSetAttribute(fno_main, cudaFuncAttributeMaxDynamicSharedMemorySize,
                         smem_bytes);
    fno_main<<<B / TILE_B, 256, smem_bytes>>>(mu, x, W1, b1, W2, b2, out);
}

// round 4
// speedup vs baseline: 2.1911x; 2.1908x over previous
#include <cuda_runtime.h>
#include <cuda_bf16.h>
#include <cstdint>

#define NM 256
#define NL 4
#define TILE_M 128

// Weights, B-format [n][k], pre-split hi/lo, pre-sliced in 64-k chunks:
// g_W[layer][term(0=hi,1=lo)][slice][n=256][k=64]
__device__ __nv_bfloat16 g_W[NL][2][4][256][64];
__device__ __nv_bfloat16 g_W1[2][256][64];
__device__ float g_k[NL][NM];

// ---------------------------------------------------------------------------
// helpers
// ---------------------------------------------------------------------------
__device__ __forceinline__ uint32_t smem_u32(const void* p) {
    uint32_t a;
    asm("{ .reg .u64 t; cvta.to.shared.u64 t, %1; cvt.u32.u64 %0, t; }"
        : "=r"(a) : "l"(p));
    return a;
}
__device__ __forceinline__ float lds_f(uint32_t a) {
    float v; asm volatile("ld.shared.f32 %0, [%1];" : "=f"(v) : "r"(a)); return v;
}
__device__ __forceinline__ void sts_f(uint32_t a, float v) {
    asm volatile("st.shared.f32 [%0], %1;" :: "r"(a), "f"(v) : "memory");
}
__device__ __forceinline__ void sts_u32(uint32_t a, uint32_t v) {
    asm volatile("st.shared.b32 [%0], %1;" :: "r"(a), "r"(v) : "memory");
}
__device__ __forceinline__ void sts_u16(uint32_t a, uint16_t v) {
    asm volatile("st.shared.b16 [%0], %1;" :: "r"(a), "h"(v) : "memory");
}
__device__ __forceinline__ void ldm_x4(uint32_t r[4], uint32_t addr) {
    asm volatile("ldmatrix.sync.aligned.m8n8.x4.shared.b16 {%0,%1,%2,%3}, [%4];"
                 : "=r"(r[0]), "=r"(r[1]), "=r"(r[2]), "=r"(r[3]) : "r"(addr));
}
__device__ __forceinline__ void mma16816(float c[4], const uint32_t a[4],
                                         uint32_t b0, uint32_t b1) {
    asm volatile("mma.sync.aligned.m16n8k16.row.col.f32.bf16.bf16.f32 "
                 "{%0,%1,%2,%3}, {%4,%5,%6,%7}, {%8,%9}, {%0,%1,%2,%3};"
                 : "+f"(c[0]), "+f"(c[1]), "+f"(c[2]), "+f"(c[3])
                 : "r"(a[0]), "r"(a[1]), "r"(a[2]), "r"(a[3]), "r"(b0), "r"(b1));
}
__device__ __forceinline__ void bf16_split(float v, uint16_t& h, uint16_t& l) {
    __nv_bfloat16 hb = __float2bfloat16(v);
    __nv_bfloat16 lb = __float2bfloat16(v - __bfloat162float(hb));
    h = __bfloat16_as_ushort(hb);
    l = __bfloat16_as_ushort(lb);
}
#define CP_WAIT1() asm volatile("cp.async.wait_group 1;" ::: "memory")
#define CP_WAIT0() asm volatile("cp.async.wait_group 0;" ::: "memory")

// ---------------------------------------------------------------------------
// weight builders
// ---------------------------------------------------------------------------
__global__ void build_mats(const float* __restrict__ fw,
                           const float* __restrict__ lw) {
    const int l = blockIdx.x;
    const int kk = threadIdx.x;                // k index 0..255
    __shared__ float ks[NM];

    const float* fwl = fw + l * (NM / 2 + 1);
    float s = fwl[0];
    #pragma unroll 4
    for (int m = 1; m < NM / 2; ++m)
        s += 2.0f * fwl[m] * cospif((float)(m * kk) * (1.0f / 128.0f));
    s += fwl[NM / 2] * ((kk & 1) ? -1.0f : 1.0f);
    const float kv = s * (1.0f / 256.0f);
    ks[kk] = kv;
    if (blockIdx.y == 0) g_k[l][kk] = kv;
    __syncthreads();

    const int slice = kk >> 6, k64 = kk & 63;
    const int n0 = blockIdx.y * 32;
    for (int nn = n0; nn < n0 + 32; ++nn) {
        float v = (kk < NM - 3) ? ks[(nn - kk - 3) & (NM - 1)] : 0.0f;
        if (kk == nn) v += lw[l * NM + nn];
        uint16_t h, lo; bf16_split(v, h, lo);
        g_W[l][0][slice][nn][k64] = __ushort_as_bfloat16(h);
        g_W[l][1][slice][nn][k64] = __ushort_as_bfloat16(lo);
    }
}

__global__ void enc_split(const float* __restrict__ W1) {
    int i = blockIdx.x * 256 + threadIdx.x;    // 16384 = 256n * 64k
    int n = i >> 6, k = i & 63;
    float v = W1[k * NM + n];
    uint16_t h, lo; bf16_split(v, h, lo);
    g_W1[0][n][k] = __ushort_as_bfloat16(h);
    g_W1[1][n][k] = __ushort_as_bfloat16(lo);
}

// ---------------------------------------------------------------------------
// SMEM layout (bytes from base)
// ---------------------------------------------------------------------------
#define A_STRIDE 528        // 256 bf16 + pad (33*16B -> ldmatrix conflict-free)
#define B_STRIDE 144        // 64 bf16 + pad (9*16B)
#define OFF_AH   0u
#define OFF_AL   67584u     // 128*528
#define OFF_B0   135168u
#define OFF_B1   172032u    // +256*144
#define OFF_K    208896u
#define OFF_B1S  209920u
#define OFF_W2   210944u
#define OFF_X    211968u    // 128*12 = 1536 (pad to 2048)
#define OFF_PS   214016u    // 128*16
#define SMEM_TOTAL 216064

// slice loader: 256 n-rows x 64 k bf16 (128B/row) -> padded SMEM
__device__ __forceinline__ void load_slice(const __nv_bfloat16* g, uint32_t sbuf,
                                           int tid) {
    #pragma unroll
    for (int it = 0; it < 8; ++it) {
        int idx = it * 256 + tid;
        int row = idx >> 3, seg = idx & 7;
        const void* src = g + row * 64 + seg * 8;
        uint32_t dst = sbuf + row * B_STRIDE + seg * 16;
        asm volatile("cp.async.cg.shared.global [%0], [%1], 16;"
                     :: "r"(dst), "l"(src) : "memory");
    }
    asm volatile("cp.async.commit_group;" ::: "memory");
}

// ---------------------------------------------------------------------------
// main kernel
// ---------------------------------------------------------------------------
__global__ __launch_bounds__(256, 1)
void fno_mma(const float* __restrict__ mu, const float* __restrict__ x,
             const float* __restrict__ b1, const float* __restrict__ b2,
             const float* __restrict__ W2, float* __restrict__ out) {
    extern __shared__ __align__(16) unsigned char smraw[];
    const uint32_t sb = smem_u32(smraw);

    const int tid = threadIdx.x;
    const int lane = tid & 31, wid = tid >> 5;
    const int wm = wid >> 2, wn = wid & 3;      // 2 x 4 warp grid (64x64 tiles)
    const int g = lane >> 2, qi = lane & 3;
    const int r8 = lane & 7, q = lane >> 3;
    const long long row0 = (long long)blockIdx.x * TILE_M;

    // ldmatrix lane address components
    const uint32_t lmRowA = (uint32_t)(r8 + (q & 1) * 8) * A_STRIDE + (q >> 1) * 16;
    const uint32_t lmRowB = (uint32_t)(r8 + (q & 1) * 8) * B_STRIDE + (q >> 1) * 16;

    // ---- stage small arrays + mu split
    sts_f(sb + OFF_B1S + tid * 4, b1[tid]);
    sts_f(sb + OFF_W2 + tid * 4, W2[tid]);
    for (int i = tid; i < TILE_M * 3; i += 256) {
        int r = i / 3, c = i % 3;
        sts_f(sb + OFF_X + (r * 3 + c) * 4, x[(row0 + r) * 3 + c]);
    }
    for (int i = tid; i < TILE_M * 64; i += 256) {
        int r = i >> 6, c = i & 63;
        float v = mu[(row0 + r) * 64 + c];
        uint16_t h, lo; bf16_split(v, h, lo);
        uint32_t off = (uint32_t)r * A_STRIDE + c * 2;
        sts_u16(sb + OFF_AH + off, h);
        sts_u16(sb + OFF_AL + off, lo);
    }

    float c[4][8][4];
    float dacc[4][2];

    for (int st = 0; st < 5; ++st) {
        const bool enc = (st == 0), dec = (st == 4);
        const int l = st - 1;

        __syncthreads();   // prev epilogue (incl. sK readers) done
        if (!enc) sts_f(sb + OFF_K + tid * 4, g_k[l][tid]);

        #pragma unroll
        for (int mt = 0; mt < 4; ++mt)
            #pragma unroll
            for (int nt = 0; nt < 8; ++nt)
                #pragma unroll
                for (int e = 0; e < 4; ++e) c[mt][nt][e] = 0.f;
        if (dec) {
            #pragma unroll
            for (int mt = 0; mt < 4; ++mt) dacc[mt][0] = dacc[mt][1] = 0.f;
        }

        const int ns = enc ? 3 : 12;
        load_slice(enc ? &g_W1[0][0][0] : &g_W[l][0][0][0][0], sb + OFF_B0, tid);

        for (int s = 0; s < ns; ++s) {
            __syncthreads();   // everyone done reading buf[(s+1)&1] (slice s-1)
            if (s + 1 < ns) {
                const int s1 = s + 1;
                const __nv_bfloat16* src;
                if (enc) src = &g_W1[(s1 == 1) ? 1 : 0][0][0];
                else {
                    int t1 = s1 >> 2;
                    src = &g_W[l][(t1 == 1) ? 1 : 0][s1 & 3][0][0];
                }
                load_slice(src, sb + ((s1 & 1) ? OFF_B1 : OFF_B0), tid);
                CP_WAIT1();
            } else {
                CP_WAIT0();
            }
            __syncthreads();   // slice s visible to all warps

            uint32_t sAsrc, koffA;
            if (enc) { sAsrc = (s == 2) ? OFF_AL : OFF_AH; koffA = 0; }
            else {
                int term = s >> 2;
                sAsrc = (term == 2) ? OFF_AL : OFF_AH;
                koffA = (uint32_t)(s & 3) * 128;
            }
            const uint32_t aBase = sb + sAsrc + (uint32_t)(wm * 64) * A_STRIDE
                                 + koffA + lmRowA;
            const uint32_t bBase = sb + ((s & 1) ? OFF_B1 : OFF_B0)
                                 + (uint32_t)(wn * 64) * B_STRIDE + lmRowB;

            #pragma unroll
            for (int kc = 0; kc < 4; ++kc) {
                uint32_t a[4][4], b[4][4];
                #pragma unroll
                for (int mt = 0; mt < 4; ++mt)
                    ldm_x4(a[mt], aBase + (uint32_t)(mt * 16) * A_STRIDE + kc * 32);
                #pragma unroll
                for (int np = 0; np < 4; ++np)
                    ldm_x4(b[np], bBase + (uint32_t)(np * 16) * B_STRIDE + kc * 32);
                #pragma unroll
                for (int mt = 0; mt < 4; ++mt)
                    #pragma unroll
                    for (int np = 0; np < 4; ++np) {
                        mma16816(c[mt][2 * np],     a[mt], b[np][0], b[np][2]);
                        mma16816(c[mt][2 * np + 1], a[mt], b[np][1], b[np][3]);
                    }
            }
        }
        __syncthreads();   // all warps done reading A before overwrite

        // ---------------- epilogue ----------------
        float xr[4][2][3];
        if (!enc) {
            #pragma unroll
            for (int mt = 0; mt < 4; ++mt)
                #pragma unroll
                for (int h = 0; h < 2; ++h) {
                    int r = wm * 64 + mt * 16 + g + h * 8;
                    #pragma unroll
                    for (int j = 0; j < 3; ++j)
                        xr[mt][h][j] = lds_f(sb + OFF_X + (r * 3 + j) * 4);
                }
        }

        #pragma unroll
        for (int nt = 0; nt < 8; ++nt) {
            const int c0 = wn * 64 + nt * 8 + qi * 2;
            float kp1 = 0.f, k0 = 0.f, km1 = 0.f, km2 = 0.f, bb0 = 0.f, bb1 = 0.f;
            if (enc) {
                bb0 = lds_f(sb + OFF_B1S + c0 * 4);
                bb1 = lds_f(sb + OFF_B1S + c0 * 4 + 4);
            } else {
                kp1 = lds_f(sb + OFF_K + (((c0 + 1) & 255) * 4));
                k0  = lds_f(sb + OFF_K + (c0 * 4));
                km1 = lds_f(sb + OFF_K + (((c0 - 1) & 255) * 4));
                km2 = lds_f(sb + OFF_K + (((c0 - 2) & 255) * 4));
            }
            float w0 = 0.f, w1 = 0.f;
            if (dec) {
                w0 = lds_f(sb + OFF_W2 + c0 * 4);
                w1 = lds_f(sb + OFF_W2 + c0 * 4 + 4);
            }
            #pragma unroll
            for (int mt = 0; mt < 4; ++mt) {
                float v0 = c[mt][nt][0], v1 = c[mt][nt][1];
                float v2 = c[mt][nt][2], v3 = c[mt][nt][3];
                if (enc) {
                    v0 += bb0; v1 += bb1; v2 += bb0; v3 += bb1;
                } else {
                    v0 += xr[mt][0][0] * k0  + xr[mt][0][1] * km1 + xr[mt][0][2] * km2;
                    v1 += xr[mt][0][0] * kp1 + xr[mt][0][1] * k0  + xr[mt][0][2] * km1;
                    v2 += xr[mt][1][0] * k0  + xr[mt][1][1] * km1 + xr[mt][1][2] * km2;
                    v3 += xr[mt][1][0] * kp1 + xr[mt][1][1] * k0  + xr[mt][1][2] * km1;
                }
                v0 = fmaxf(v0, 0.f); v1 = fmaxf(v1, 0.f);
                v2 = fmaxf(v2, 0.f); v3 = fmaxf(v3, 0.f);
                if (!dec) {
                    uint16_t h0, l0, h1, l1;
                    const int r0 = wm * 64 + mt * 16 + g;
                    uint32_t o0 = (uint32_t)r0 * A_STRIDE + c0 * 2;
                    bf16_split(v0, h0, l0); bf16_split(v1, h1, l1);
                    sts_u32(sb + OFF_AH + o0, (uint32_t)h0 | ((uint32_t)h1 << 16));
                    sts_u32(sb + OFF_AL + o0, (uint32_t)l0 | ((uint32_t)l1 << 16));
                    bf16_split(v2, h0, l0); bf16_split(v3, h1, l1);
                    uint32_t o1 = o0 + 8u * A_STRIDE;
                    sts_u32(sb + OFF_AH + o1, (uint32_t)h0 | ((uint32_t)h1 << 16));
                    sts_u32(sb + OFF_AL + o1, (uint32_t)l0 | ((uint32_t)l1 << 16));
                } else {
                    dacc[mt][0] += v0 * w0 + v1 * w1;
                    dacc[mt][1] += v2 * w0 + v3 * w1;
                }
            }
        }

        if (dec) {
            #pragma unroll
            for (int mt = 0; mt < 4; ++mt)
                #pragma unroll
                for (int h = 0; h < 2; ++h) {
                    float s = dacc[mt][h];
                    s += __shfl_xor_sync(0xffffffffu, s, 1);
                    s += __shfl_xor_sync(0xffffffffu, s, 2);
                    if (qi == 0) {
                        int r = wm * 64 + mt * 16 + g + h * 8;
                        sts_f(sb + OFF_PS + r * 16 + wn * 4, s);
                    }
                }
            __syncthreads();
            if (tid < TILE_M) {
                float o = lds_f(sb + OFF_PS + tid * 16)
                        + lds_f(sb + OFF_PS + tid * 16 + 4)
                        + lds_f(sb + OFF_PS + tid * 16 + 8)
                        + lds_f(sb + OFF_PS + tid * 16 + 12);
                out[row0 + tid] = o + b2[0];
            }
        }
    }
}

// ---------------------------------------------------------------------------
extern "C" void kernel_launch(void* const* d_in, const int* in_sizes, int n_in,
                              void* d_out, int out_size) {
    const float* mu = (const float*)d_in[0];
    const float* x  = (const float*)d_in[1];
    const float* W1 = (const float*)d_in[2];
    const float* b1 = (const float*)d_in[3];
    const float* fw = (const float*)d_in[4];
    const float* lw = (const float*)d_in[5];
    const float* W2 = (const float*)d_in[6];
    const float* b2 = (const float*)d_in[7];
    float* out = (float*)d_out;

    const int B = in_sizes[0] / 64;

    build_mats<<<dim3(NL, 8), NM>>>(fw, lw);
    enc_split<<<64, 256>>>(W1);

    cudaFuncSetAttribute(fno_mma, cudaFuncAttributeMaxDynamicSharedMemorySize,
                         SMEM_TOTAL);
    fno_mma<<<B / TILE_M, 256, SMEM_TOTAL>>>(mu, x, b1, b2, W2, out);
}

// round 6
// speedup vs baseline: 2.1954x; 1.0020x over previous
#include <cuda_runtime.h>
#include <cuda_bf16.h>
#include <cstdint>

#define NM 256
#define NL 4
#define TILE_M 128

// Circulant tall tiles Btall[m][j] = c[(m-j-3)&255], bf16 hi/lo.
__device__ __nv_bfloat16 g_Bc[NL][2][256][64];
__device__ __nv_bfloat16 g_W1[2][256][64];
__device__ float g_lwv[NL][NM];

// ---------------------------------------------------------------------------
__device__ __forceinline__ uint32_t smem_u32(const void* p) {
    uint32_t a;
    asm("{ .reg .u64 t; cvta.to.shared.u64 t, %1; cvt.u32.u64 %0, t; }"
        : "=r"(a) : "l"(p));
    return a;
}
__device__ __forceinline__ float lds_f(uint32_t a) {
    float v; asm volatile("ld.shared.f32 %0, [%1];" : "=f"(v) : "r"(a)); return v;
}
__device__ __forceinline__ uint32_t lds_u32(uint32_t a) {
    uint32_t v; asm volatile("ld.shared.b32 %0, [%1];" : "=r"(v) : "r"(a)); return v;
}
__device__ __forceinline__ uint16_t lds_u16(uint32_t a) {
    uint16_t v; asm volatile("ld.shared.u16 %0, [%1];" : "=h"(v) : "r"(a)); return v;
}
__device__ __forceinline__ void sts_f(uint32_t a, float v) {
    asm volatile("st.shared.f32 [%0], %1;" :: "r"(a), "f"(v) : "memory");
}
__device__ __forceinline__ void sts_u32(uint32_t a, uint32_t v) {
    asm volatile("st.shared.b32 [%0], %1;" :: "r"(a), "r"(v) : "memory");
}
__device__ __forceinline__ void sts_u16(uint32_t a, uint16_t v) {
    asm volatile("st.shared.b16 [%0], %1;" :: "r"(a), "h"(v) : "memory");
}
__device__ __forceinline__ void ldm_x4(uint32_t r[4], uint32_t addr) {
    asm volatile("ldmatrix.sync.aligned.m8n8.x4.shared.b16 {%0,%1,%2,%3}, [%4];"
                 : "=r"(r[0]), "=r"(r[1]), "=r"(r[2]), "=r"(r[3]) : "r"(addr));
}
__device__ __forceinline__ void mma16816(float c[4], const uint32_t a[4],
                                         uint32_t b0, uint32_t b1) {
    asm volatile("mma.sync.aligned.m16n8k16.row.col.f32.bf16.bf16.f32 "
                 "{%0,%1,%2,%3}, {%4,%5,%6,%7}, {%8,%9}, {%0,%1,%2,%3};"
                 : "+f"(c[0]), "+f"(c[1]), "+f"(c[2]), "+f"(c[3])
                 : "r"(a[0]), "r"(a[1]), "r"(a[2]), "r"(a[3]), "r"(b0), "r"(b1));
}
__device__ __forceinline__ void bf16_split(float v, uint16_t& h, uint16_t& l) {
    __nv_bfloat16 hb = __float2bfloat16(v);
    __nv_bfloat16 lb = __float2bfloat16(v - __bfloat162float(hb));
    h = __bfloat16_as_ushort(hb);
    l = __bfloat16_as_ushort(lb);
}
__device__ __forceinline__ float bfu(uint16_t u) {
    return __bfloat162float(__ushort_as_bfloat16(u));
}
#define CP_WAIT0() asm volatile("cp.async.wait_group 0;" ::: "memory")

// ---------------------------------------------------------------------------
// build: c = irfft(fw); Btall[m][j] = c[(m-j-3)&255] hi/lo; lw copied.
// ---------------------------------------------------------------------------
__global__ void build_mats(const float* __restrict__ fw,
                           const float* __restrict__ lw) {
    const int l = blockIdx.x;
    const int kk = threadIdx.x;
    __shared__ float ks[NM];

    const float* fwl = fw + l * (NM / 2 + 1);
    float s = fwl[0];
    #pragma unroll 4
    for (int m = 1; m < NM / 2; ++m)
        s += 2.0f * fwl[m] * cospif((float)(m * kk) * (1.0f / 128.0f));
    s += fwl[NM / 2] * ((kk & 1) ? -1.0f : 1.0f);
    ks[kk] = s * (1.0f / 256.0f);
    if (blockIdx.y == 0) g_lwv[l][kk] = lw[l * NM + kk];
    __syncthreads();

    const int m0 = blockIdx.y * 32;
    for (int idx = kk; idx < 32 * 64; idx += 256) {
        int m = m0 + (idx >> 6), j = idx & 63;
        float v = ks[(m - j - 3) & (NM - 1)];
        uint16_t h, lo; bf16_split(v, h, lo);
        g_Bc[l][0][m][j] = __ushort_as_bfloat16(h);
        g_Bc[l][1][m][j] = __ushort_as_bfloat16(lo);
    }
}

__global__ void enc_split(const float* __restrict__ W1) {
    int i = blockIdx.x * 256 + threadIdx.x;
    int n = i >> 6, k = i & 63;
    float v = W1[k * NM + n];
    uint16_t h, lo; bf16_split(v, h, lo);
    g_W1[0][n][k] = __ushort_as_bfloat16(h);
    g_W1[1][n][k] = __ushort_as_bfloat16(lo);
}

// ---------------------------------------------------------------------------
// SMEM map
// ---------------------------------------------------------------------------
#define A_ST 512
#define OFF_AH 0u
#define OFF_AL 65536u
#define OFF_B0 131072u
#define OFF_B1 163840u
#define OFF_LW 196608u
#define OFF_BB 197632u
#define OFF_W2 198656u
#define OFF_X  199680u
#define OFF_HS 201216u
#define OFF_PS 202752u
#define SMEM_TOTAL 204800

// 32KB circulant tile loader (128B rows, XOR-swizzled 16B chunks)
__device__ __forceinline__ void load_tile(const __nv_bfloat16* g, uint32_t sbuf,
                                          int tid) {
    #pragma unroll
    for (int it = 0; it < 8; ++it) {
        int idx = it * 256 + tid;
        int row = idx >> 3, seg = idx & 7;
        const void* src = g + row * 64 + seg * 8;
        uint32_t dst = sbuf + row * 128 + ((seg * 16) ^ ((row & 7) * 16));
        asm volatile("cp.async.cg.shared.global [%0], [%1], 16;"
                     :: "r"(dst), "l"(src) : "memory");
    }
    asm volatile("cp.async.commit_group;" ::: "memory");
}

// ---------------------------------------------------------------------------
__global__ __launch_bounds__(256, 1)
void fno_mma(const float* __restrict__ mu, const float* __restrict__ x,
             const float* __restrict__ b1, const float* __restrict__ b2,
             const float* __restrict__ W2, float* __restrict__ out) {
    extern __shared__ __align__(16) unsigned char smraw[];
    const uint32_t sb = smem_u32(smraw);

    const int tid = threadIdx.x;
    const int lane = tid & 31, wid = tid >> 5;
    const int wm = wid >> 2, wn = wid & 3;
    const int g = lane >> 2, qi = lane & 3;
    const int r8 = lane & 7, q = lane >> 3;
    const long long row0 = (long long)blockIdx.x * TILE_M;

    // ldmatrix lane bases
    const int rA0 = wm * 64 + r8 + (q & 1) * 8;
    const uint32_t swA = (uint32_t)(rA0 & 7) * 16;
    const int rB0 = wn * 64 + r8 + (q & 1) * 8;
    const uint32_t swB = (uint32_t)(rB0 & 7) * 16;
    const uint32_t cB16 = (uint32_t)(q >> 1) * 16;

    // kick encoder weight tiles
    load_tile(&g_W1[0][0][0], sb + OFF_B0, tid);
    load_tile(&g_W1[1][0][0], sb + OFF_B1, tid);

    // stage scalars
    sts_f(sb + OFF_BB + tid * 4, b1[tid]);
    sts_f(sb + OFF_W2 + tid * 4, W2[tid]);
    for (int i = tid; i < TILE_M * 3; i += 256) {
        int r = i / 3, c = i % 3;
        sts_f(sb + OFF_X + (r * 3 + c) * 4, x[(row0 + r) * 3 + c]);
    }
    // stage mu (cols 0-63 of A, split)
    {
        const float2* mu2 = (const float2*)(mu + row0 * 64);
        for (int i = tid; i < TILE_M * 32; i += 256) {
            int r = i >> 5, c2 = i & 31;
            float2 v = mu2[r * 32 + c2];
            uint16_t h0, l0, h1, l1;
            bf16_split(v.x, h0, l0); bf16_split(v.y, h1, l1);
            uint32_t off = (uint32_t)r * A_ST + ((uint32_t)(c2 * 4) ^ ((r & 7) * 16));
            sts_u32(sb + OFF_AH + off, (uint32_t)h0 | ((uint32_t)h1 << 16));
            sts_u32(sb + OFF_AL + off, (uint32_t)l0 | ((uint32_t)l1 << 16));
        }
    }

    float c[4][8][4];
    float dacc[4][2];

    for (int st = 0; st < 5; ++st) {
        const bool enc = (st == 0), dec = (st == 4);
        const int l = st - 1;

        CP_WAIT0();
        __syncthreads();                 // B tiles ready, prev epilogue done
        if (!enc) sts_f(sb + OFF_LW + tid * 4, g_lwv[l][tid]);

        #pragma unroll
        for (int mt = 0; mt < 4; ++mt)
            #pragma unroll
            for (int nt = 0; nt < 8; ++nt)
                #pragma unroll
                for (int e = 0; e < 4; ++e) c[mt][nt][e] = 0.f;
        if (dec) {
            #pragma unroll
            for (int mt = 0; mt < 4; ++mt) dacc[mt][0] = dacc[mt][1] = 0.f;
        }

        const int ns = enc ? 1 : 4;
        for (int s = 0; s < ns; ++s) {
            // B row base for this slice (circulant rotation)
            const int rBs = (rB0 - 64 * s) & 255;
            const uint32_t bRow = sb + (uint32_t)rBs * 128;
            const uint32_t aCol0 = (uint32_t)s * 128 + cB16;
            #pragma unroll
            for (int kc = 0; kc < 4; ++kc) {
                const uint32_t aCsw = ((aCol0 + kc * 32) ^ swA);
                const uint32_t bCsw = (((uint32_t)kc * 32 + cB16) ^ swB);
                uint32_t aH[4][4], b0f[4][4], b1f[4][4];
                #pragma unroll
                for (int mt = 0; mt < 4; ++mt)
                    ldm_x4(aH[mt], sb + OFF_AH + (uint32_t)(rA0 + mt * 16) * A_ST + aCsw);
                #pragma unroll
                for (int np = 0; np < 4; ++np) {
                    uint32_t ro = (uint32_t)(((rBs + np * 16) & 255)) * 128;
                    ldm_x4(b0f[np], sb + OFF_B0 + ro + bCsw);
                    ldm_x4(b1f[np], sb + OFF_B1 + ro + bCsw);
                }
                #pragma unroll
                for (int mt = 0; mt < 4; ++mt)
                    #pragma unroll
                    for (int np = 0; np < 4; ++np) {
                        mma16816(c[mt][2 * np],     aH[mt], b0f[np][0], b0f[np][2]);
                        mma16816(c[mt][2 * np + 1], aH[mt], b0f[np][1], b0f[np][3]);
                        mma16816(c[mt][2 * np],     aH[mt], b1f[np][0], b1f[np][2]);
                        mma16816(c[mt][2 * np + 1], aH[mt], b1f[np][1], b1f[np][3]);
                    }
                uint32_t aL[4];
                #pragma unroll
                for (int mt = 0; mt < 4; ++mt) {
                    ldm_x4(aL, sb + OFF_AL + (uint32_t)(rA0 + mt * 16) * A_ST + aCsw);
                    #pragma unroll
                    for (int np = 0; np < 4; ++np) {
                        mma16816(c[mt][2 * np],     aL, b0f[np][0], b0f[np][2]);
                        mma16816(c[mt][2 * np + 1], aL, b0f[np][1], b0f[np][3]);
                    }
                }
            }
        }
        __syncthreads();                 // all warps done reading A and B

        if (st < 4) {                    // prefetch next layer's tiles
            load_tile(&g_Bc[st][0][0][0], sb + OFF_B0, tid);
            load_tile(&g_Bc[st][1][0][0], sb + OFF_B1, tid);
        }

        // -------- epilogue (race-free: each (r,n) owned by one thread) -----
        #pragma unroll
        for (int nt = 0; nt < 8; ++nt) {
            const int c0 = wn * 64 + nt * 8 + qi * 2;
            float lw0 = 0.f, lw1 = 0.f, bb0 = 0.f, bb1 = 0.f, w0 = 0.f, w1 = 0.f;
            if (enc) {
                bb0 = lds_f(sb + OFF_BB + c0 * 4);
                bb1 = lds_f(sb + OFF_BB + c0 * 4 + 4);
            } else {
                lw0 = lds_f(sb + OFF_LW + c0 * 4);
                lw1 = lds_f(sb + OFF_LW + c0 * 4 + 4);
            }
            if (dec) {
                w0 = lds_f(sb + OFF_W2 + c0 * 4);
                w1 = lds_f(sb + OFF_W2 + c0 * 4 + 4);
            }
            #pragma unroll
            for (int mt = 0; mt < 4; ++mt)
                #pragma unroll
                for (int h = 0; h < 2; ++h) {
                    const int r = wm * 64 + mt * 16 + g + h * 8;
                    const uint32_t swr = (uint32_t)(r & 7) * 16;
                    const uint32_t rbase = (uint32_t)r * A_ST;
                    float v0 = c[mt][nt][2 * h], v1 = c[mt][nt][2 * h + 1];

                    if (enc) {
                        v0 += bb0; v1 += bb1;
                    } else {
                        float hp0, hp1;
                        if (c0 < 252) {
                            uint32_t uh = lds_u32(sb + OFF_AH + rbase + (((uint32_t)c0 * 2) ^ swr));
                            uint32_t ul = lds_u32(sb + OFF_AL + rbase + (((uint32_t)c0 * 2) ^ swr));
                            hp0 = bfu((uint16_t)uh) + bfu((uint16_t)ul);
                            hp1 = bfu((uint16_t)(uh >> 16)) + bfu((uint16_t)(ul >> 16));
                        } else {
                            hp0 = (c0 < 253)
                                ? bfu(lds_u16(sb + OFF_AH + rbase + (((uint32_t)c0 * 2) ^ swr)))
                                  + bfu(lds_u16(sb + OFF_AL + rbase + (((uint32_t)c0 * 2) ^ swr)))
                                : lds_f(sb + OFF_HS + (r * 3 + c0 - 253) * 4);
                            hp1 = (c0 + 1 < 253)
                                ? 0.f
                                : lds_f(sb + OFF_HS + (r * 3 + c0 + 1 - 253) * 4);
                        }
                        v0 += lw0 * hp0; v1 += lw1 * hp1;
                    }
                    v0 = fmaxf(v0, 0.f); v1 = fmaxf(v1, 0.f);

                    if (dec) {
                        dacc[mt][h] += v0 * w0 + v1 * w1;
                    } else if (c0 < 252) {
                        uint16_t h0, l0, h1, l1;
                        bf16_split(v0, h0, l0); bf16_split(v1, h1, l1);
                        uint32_t off = rbase + (((uint32_t)c0 * 2) ^ swr);
                        sts_u32(sb + OFF_AH + off, (uint32_t)h0 | ((uint32_t)h1 << 16));
                        sts_u32(sb + OFF_AL + off, (uint32_t)l0 | ((uint32_t)l1 << 16));
                    } else {
                        #pragma unroll
                        for (int e = 0; e < 2; ++e) {
                            int n = c0 + e;
                            float v = e ? v1 : v0;
                            if (n < 253) {
                                uint16_t hh, ll; bf16_split(v, hh, ll);
                                uint32_t off = rbase + (((uint32_t)n * 2) ^ swr);
                                sts_u16(sb + OFF_AH + off, hh);
                                sts_u16(sb + OFF_AL + off, ll);
                            } else {
                                sts_f(sb + OFF_HS + (r * 3 + n - 253) * 4, v);
                                if (enc) {
                                    float xv = lds_f(sb + OFF_X + (r * 3 + n - 253) * 4);
                                    uint16_t hh, ll; bf16_split(xv, hh, ll);
                                    uint32_t off = rbase + (((uint32_t)n * 2) ^ swr);
                                    sts_u16(sb + OFF_AH + off, hh);
                                    sts_u16(sb + OFF_AL + off, ll);
                                }
                            }
                        }
                    }
                }
        }

        if (dec) {
            #pragma unroll
            for (int mt = 0; mt < 4; ++mt)
                #pragma unroll
                for (int h = 0; h < 2; ++h) {
                    float s = dacc[mt][h];
                    s += __shfl_xor_sync(0xffffffffu, s, 1);
                    s += __shfl_xor_sync(0xffffffffu, s, 2);
                    if (qi == 0) {
                        int r = wm * 64 + mt * 16 + g + h * 8;
                        sts_f(sb + OFF_PS + r * 16 + wn * 4, s);
                    }
                }
            __syncthreads();
            if (tid < TILE_M) {
                float o = lds_f(sb + OFF_PS + tid * 16)
                        + lds_f(sb + OFF_PS + tid * 16 + 4)
                        + lds_f(sb + OFF_PS + tid * 16 + 8)
                        + lds_f(sb + OFF_PS + tid * 16 + 12);
                out[row0 + tid] = o + b2[0];
            }
        }
    }
}

// ---------------------------------------------------------------------------
extern "C" void kernel_launch(void* const* d_in, const int* in_sizes, int n_in,
                              void* d_out, int out_size) {
    const float* mu = (const float*)d_in[0];
    const float* x  = (const float*)d_in[1];
    const float* W1 = (const float*)d_in[2];
    const float* b1 = (const float*)d_in[3];
    const float* fw = (const float*)d_in[4];
    const float* lw = (const float*)d_in[5];
    const float* W2 = (const float*)d_in[6];
    const float* b2 = (const float*)d_in[7];
    float* out = (float*)d_out;

    const int B = in_sizes[0] / 64;

    build_mats<<<dim3(NL, 8), NM>>>(fw, lw);
    enc_split<<<64, 256>>>(W1);

    cudaFuncSetAttribute(fno_mma, cudaFuncAttributeMaxDynamicSharedMemorySize,
                         SMEM_TOTAL);
    fno_mma<<<B / TILE_M, 256, SMEM_TOTAL>>>(mu, x, b1, b2, W2, out);
}

// round 7
// speedup vs baseline: 2.1978x; 1.0011x over previous
#include <cuda_runtime.h>
#include <cuda_bf16.h>
#include <cstdint>

#define NM 256
#define NL 4
#define TILE_M 128

// Circulant tall tiles Btall[m][j] = c[(m-j-3)&255], bf16 hi/lo.
__device__ __nv_bfloat16 g_Bc[NL][2][256][64];
__device__ __nv_bfloat16 g_W1[2][256][64];
__device__ float g_lwv[NL][NM];

// ---------------------------------------------------------------------------
__device__ __forceinline__ uint32_t smem_u32(const void* p) {
    uint32_t a;
    asm("{ .reg .u64 t; cvta.to.shared.u64 t, %1; cvt.u32.u64 %0, t; }"
        : "=r"(a) : "l"(p));
    return a;
}
__device__ __forceinline__ float lds_f(uint32_t a) {
    float v; asm volatile("ld.shared.f32 %0, [%1];" : "=f"(v) : "r"(a)); return v;
}
__device__ __forceinline__ uint32_t lds_u32(uint32_t a) {
    uint32_t v; asm volatile("ld.shared.b32 %0, [%1];" : "=r"(v) : "r"(a)); return v;
}
__device__ __forceinline__ uint16_t lds_u16(uint32_t a) {
    uint16_t v; asm volatile("ld.shared.u16 %0, [%1];" : "=h"(v) : "r"(a)); return v;
}
__device__ __forceinline__ void sts_f(uint32_t a, float v) {
    asm volatile("st.shared.f32 [%0], %1;" :: "r"(a), "f"(v) : "memory");
}
__device__ __forceinline__ void sts_u32(uint32_t a, uint32_t v) {
    asm volatile("st.shared.b32 [%0], %1;" :: "r"(a), "r"(v) : "memory");
}
__device__ __forceinline__ void sts_u16(uint32_t a, uint16_t v) {
    asm volatile("st.shared.b16 [%0], %1;" :: "r"(a), "h"(v) : "memory");
}
__device__ __forceinline__ void ldm_x4(uint32_t r[4], uint32_t addr) {
    asm volatile("ldmatrix.sync.aligned.m8n8.x4.shared.b16 {%0,%1,%2,%3}, [%4];"
                 : "=r"(r[0]), "=r"(r[1]), "=r"(r[2]), "=r"(r[3]) : "r"(addr));
}
__device__ __forceinline__ void mma16816(float c[4], const uint32_t a[4],
                                         uint32_t b0, uint32_t b1) {
    asm volatile("mma.sync.aligned.m16n8k16.row.col.f32.bf16.bf16.f32 "
                 "{%0,%1,%2,%3}, {%4,%5,%6,%7}, {%8,%9}, {%0,%1,%2,%3};"
                 : "+f"(c[0]), "+f"(c[1]), "+f"(c[2]), "+f"(c[3])
                 : "r"(a[0]), "r"(a[1]), "r"(a[2]), "r"(a[3]), "r"(b0), "r"(b1));
}
__device__ __forceinline__ void bf16_split(float v, uint16_t& h, uint16_t& l) {
    __nv_bfloat16 hb = __float2bfloat16(v);
    __nv_bfloat16 lb = __float2bfloat16(v - __bfloat162float(hb));
    h = __bfloat16_as_ushort(hb);
    l = __bfloat16_as_ushort(lb);
}
__device__ __forceinline__ float bfu(uint16_t u) {
    return __bfloat162float(__ushort_as_bfloat16(u));
}
#define CP_WAIT0() asm volatile("cp.async.wait_group 0;" ::: "memory")

// ---------------------------------------------------------------------------
// build: c = irfft(fw); Btall[m][j] = c[(m-j-3)&255] hi/lo; lw copied.
// ---------------------------------------------------------------------------
__global__ void build_mats(const float* __restrict__ fw,
                           const float* __restrict__ lw) {
    const int l = blockIdx.x;
    const int kk = threadIdx.x;
    __shared__ float ks[NM];

    const float* fwl = fw + l * (NM / 2 + 1);
    float s = fwl[0];
    #pragma unroll 4
    for (int m = 1; m < NM / 2; ++m)
        s += 2.0f * fwl[m] * cospif((float)(m * kk) * (1.0f / 128.0f));
    s += fwl[NM / 2] * ((kk & 1) ? -1.0f : 1.0f);
    ks[kk] = s * (1.0f / 256.0f);
    if (blockIdx.y == 0) g_lwv[l][kk] = lw[l * NM + kk];
    __syncthreads();

    const int m0 = blockIdx.y * 32;
    for (int idx = kk; idx < 32 * 64; idx += 256) {
        int m = m0 + (idx >> 6), j = idx & 63;
        float v = ks[(m - j - 3) & (NM - 1)];
        uint16_t h, lo; bf16_split(v, h, lo);
        g_Bc[l][0][m][j] = __ushort_as_bfloat16(h);
        g_Bc[l][1][m][j] = __ushort_as_bfloat16(lo);
    }
}

__global__ void enc_split(const float* __restrict__ W1) {
    int i = blockIdx.x * 256 + threadIdx.x;
    int n = i >> 6, k = i & 63;
    float v = W1[k * NM + n];
    uint16_t h, lo; bf16_split(v, h, lo);
    g_W1[0][n][k] = __ushort_as_bfloat16(h);
    g_W1[1][n][k] = __ushort_as_bfloat16(lo);
}

// ---------------------------------------------------------------------------
// SMEM map
// ---------------------------------------------------------------------------
#define A_ST 512
#define OFF_AH 0u
#define OFF_AL 65536u
#define OFF_B0 131072u
#define OFF_B1 163840u
#define OFF_LW 196608u
#define OFF_BB 197632u
#define OFF_W2 198656u
#define OFF_X  199680u
#define OFF_HS 201216u
#define OFF_PS 202752u
#define SMEM_TOTAL 204800

// 32KB circulant tile loader (128B rows, XOR-swizzled 16B chunks)
__device__ __forceinline__ void load_tile(const __nv_bfloat16* g, uint32_t sbuf,
                                          int tid) {
    #pragma unroll
    for (int it = 0; it < 8; ++it) {
        int idx = it * 256 + tid;
        int row = idx >> 3, seg = idx & 7;
        const void* src = g + row * 64 + seg * 8;
        uint32_t dst = sbuf + row * 128 + ((seg * 16) ^ ((row & 7) * 16));
        asm volatile("cp.async.cg.shared.global [%0], [%1], 16;"
                     :: "r"(dst), "l"(src) : "memory");
    }
    asm volatile("cp.async.commit_group;" ::: "memory");
}

// ---------------------------------------------------------------------------
__global__ __launch_bounds__(256, 1)
void fno_mma(const float* __restrict__ mu, const float* __restrict__ x,
             const float* __restrict__ b1, const float* __restrict__ b2,
             const float* __restrict__ W2, float* __restrict__ out) {
    extern __shared__ __align__(16) unsigned char smraw[];
    const uint32_t sb = smem_u32(smraw);

    const int tid = threadIdx.x;
    const int lane = tid & 31, wid = tid >> 5;
    const int wm = wid >> 2, wn = wid & 3;
    const int g = lane >> 2, qi = lane & 3;
    const int r8 = lane & 7, q = lane >> 3;
    const long long row0 = (long long)blockIdx.x * TILE_M;

    // ldmatrix lane bases
    const int rA0 = wm * 64 + r8 + (q & 1) * 8;
    const uint32_t swA = (uint32_t)(rA0 & 7) * 16;
    const int rB0 = wn * 64 + r8 + (q & 1) * 8;
    const uint32_t swB = (uint32_t)(rB0 & 7) * 16;
    const uint32_t cB16 = (uint32_t)(q >> 1) * 16;

    // kick encoder weight tiles
    load_tile(&g_W1[0][0][0], sb + OFF_B0, tid);
    load_tile(&g_W1[1][0][0], sb + OFF_B1, tid);

    // stage scalars
    sts_f(sb + OFF_BB + tid * 4, b1[tid]);
    sts_f(sb + OFF_W2 + tid * 4, W2[tid]);
    for (int i = tid; i < TILE_M * 3; i += 256) {
        int r = i / 3, c = i % 3;
        sts_f(sb + OFF_X + (r * 3 + c) * 4, x[(row0 + r) * 3 + c]);
    }
    // stage mu (cols 0-63 of A, split)
    {
        const float2* mu2 = (const float2*)(mu + row0 * 64);
        for (int i = tid; i < TILE_M * 32; i += 256) {
            int r = i >> 5, c2 = i & 31;
            float2 v = mu2[r * 32 + c2];
            uint16_t h0, l0, h1, l1;
            bf16_split(v.x, h0, l0); bf16_split(v.y, h1, l1);
            uint32_t off = (uint32_t)r * A_ST + ((uint32_t)(c2 * 4) ^ ((r & 7) * 16));
            sts_u32(sb + OFF_AH + off, (uint32_t)h0 | ((uint32_t)h1 << 16));
            sts_u32(sb + OFF_AL + off, (uint32_t)l0 | ((uint32_t)l1 << 16));
        }
    }

    float c[4][8][4];
    float dacc[4][2];

    for (int st = 0; st < 5; ++st) {
        const bool enc = (st == 0), dec = (st == 4);
        const int l = st - 1;

        CP_WAIT0();
        __syncthreads();                 // B tiles ready, prev epilogue done
        if (!enc) sts_f(sb + OFF_LW + tid * 4, g_lwv[l][tid]);

        #pragma unroll
        for (int mt = 0; mt < 4; ++mt)
            #pragma unroll
            for (int nt = 0; nt < 8; ++nt)
                #pragma unroll
                for (int e = 0; e < 4; ++e) c[mt][nt][e] = 0.f;
        if (dec) {
            #pragma unroll
            for (int mt = 0; mt < 4; ++mt) dacc[mt][0] = dacc[mt][1] = 0.f;
        }

        const int ns = enc ? 1 : 4;
        for (int s = 0; s < ns; ++s) {
            // B row base for this slice (circulant rotation)
            const int rBs = (rB0 - 64 * s) & 255;
            const uint32_t bRow = sb + (uint32_t)rBs * 128;
            const uint32_t aCol0 = (uint32_t)s * 128 + cB16;
            #pragma unroll
            for (int kc = 0; kc < 4; ++kc) {
                const uint32_t aCsw = ((aCol0 + kc * 32) ^ swA);
                const uint32_t bCsw = (((uint32_t)kc * 32 + cB16) ^ swB);
                uint32_t aH[4][4], b0f[4][4], b1f[4][4];
                #pragma unroll
                for (int mt = 0; mt < 4; ++mt)
                    ldm_x4(aH[mt], sb + OFF_AH + (uint32_t)(rA0 + mt * 16) * A_ST + aCsw);
                #pragma unroll
                for (int np = 0; np < 4; ++np) {
                    uint32_t ro = (uint32_t)(((rBs + np * 16) & 255)) * 128;
                    ldm_x4(b0f[np], sb + OFF_B0 + ro + bCsw);
                    ldm_x4(b1f[np], sb + OFF_B1 + ro + bCsw);
                }
                #pragma unroll
                for (int mt = 0; mt < 4; ++mt)
                    #pragma unroll
                    for (int np = 0; np < 4; ++np) {
                        mma16816(c[mt][2 * np],     aH[mt], b0f[np][0], b0f[np][2]);
                        mma16816(c[mt][2 * np + 1], aH[mt], b0f[np][1], b0f[np][3]);
                        mma16816(c[mt][2 * np],     aH[mt], b1f[np][0], b1f[np][2]);
                        mma16816(c[mt][2 * np + 1], aH[mt], b1f[np][1], b1f[np][3]);
                    }
                uint32_t aL[4];
                #pragma unroll
                for (int mt = 0; mt < 4; ++mt) {
                    ldm_x4(aL, sb + OFF_AL + (uint32_t)(rA0 + mt * 16) * A_ST + aCsw);
                    #pragma unroll
                    for (int np = 0; np < 4; ++np) {
                        mma16816(c[mt][2 * np],     aL, b0f[np][0], b0f[np][2]);
                        mma16816(c[mt][2 * np + 1], aL, b0f[np][1], b0f[np][3]);
                    }
                }
            }
        }
        __syncthreads();                 // all warps done reading A and B

        if (st < 4) {                    // prefetch next layer's tiles
            load_tile(&g_Bc[st][0][0][0], sb + OFF_B0, tid);
            load_tile(&g_Bc[st][1][0][0], sb + OFF_B1, tid);
        }

        // -------- epilogue (race-free: each (r,n) owned by one thread) -----
        #pragma unroll
        for (int nt = 0; nt < 8; ++nt) {
            const int c0 = wn * 64 + nt * 8 + qi * 2;
            float lw0 = 0.f, lw1 = 0.f, bb0 = 0.f, bb1 = 0.f, w0 = 0.f, w1 = 0.f;
            if (enc) {
                bb0 = lds_f(sb + OFF_BB + c0 * 4);
                bb1 = lds_f(sb + OFF_BB + c0 * 4 + 4);
            } else {
                lw0 = lds_f(sb + OFF_LW + c0 * 4);
                lw1 = lds_f(sb + OFF_LW + c0 * 4 + 4);
            }
            if (dec) {
                w0 = lds_f(sb + OFF_W2 + c0 * 4);
                w1 = lds_f(sb + OFF_W2 + c0 * 4 + 4);
            }
            #pragma unroll
            for (int mt = 0; mt < 4; ++mt)
                #pragma unroll
                for (int h = 0; h < 2; ++h) {
                    const int r = wm * 64 + mt * 16 + g + h * 8;
                    const uint32_t swr = (uint32_t)(r & 7) * 16;
                    const uint32_t rbase = (uint32_t)r * A_ST;
                    float v0 = c[mt][nt][2 * h], v1 = c[mt][nt][2 * h + 1];

                    if (enc) {
                        v0 += bb0; v1 += bb1;
                    } else {
                        float hp0, hp1;
                        if (c0 < 252) {
                            uint32_t uh = lds_u32(sb + OFF_AH + rbase + (((uint32_t)c0 * 2) ^ swr));
                            uint32_t ul = lds_u32(sb + OFF_AL + rbase + (((uint32_t)c0 * 2) ^ swr));
                            hp0 = bfu((uint16_t)uh) + bfu((uint16_t)ul);
                            hp1 = bfu((uint16_t)(uh >> 16)) + bfu((uint16_t)(ul >> 16));
                        } else {
                            hp0 = (c0 < 253)
                                ? bfu(lds_u16(sb + OFF_AH + rbase + (((uint32_t)c0 * 2) ^ swr)))
                                  + bfu(lds_u16(sb + OFF_AL + rbase + (((uint32_t)c0 * 2) ^ swr)))
                                : lds_f(sb + OFF_HS + (r * 3 + c0 - 253) * 4);
                            hp1 = (c0 + 1 < 253)
                                ? 0.f
                                : lds_f(sb + OFF_HS + (r * 3 + c0 + 1 - 253) * 4);
                        }
                        v0 += lw0 * hp0; v1 += lw1 * hp1;
                    }
                    v0 = fmaxf(v0, 0.f); v1 = fmaxf(v1, 0.f);

                    if (dec) {
                        dacc[mt][h] += v0 * w0 + v1 * w1;
                    } else if (c0 < 252) {
                        uint16_t h0, l0, h1, l1;
                        bf16_split(v0, h0, l0); bf16_split(v1, h1, l1);
                        uint32_t off = rbase + (((uint32_t)c0 * 2) ^ swr);
                        sts_u32(sb + OFF_AH + off, (uint32_t)h0 | ((uint32_t)h1 << 16));
                        sts_u32(sb + OFF_AL + off, (uint32_t)l0 | ((uint32_t)l1 << 16));
                    } else {
                        #pragma unroll
                        for (int e = 0; e < 2; ++e) {
                            int n = c0 + e;
                            float v = e ? v1 : v0;
                            if (n < 253) {
                                uint16_t hh, ll; bf16_split(v, hh, ll);
                                uint32_t off = rbase + (((uint32_t)n * 2) ^ swr);
                                sts_u16(sb + OFF_AH + off, hh);
                                sts_u16(sb + OFF_AL + off, ll);
                            } else {
                                sts_f(sb + OFF_HS + (r * 3 + n - 253) * 4, v);
                                if (enc) {
                                    float xv = lds_f(sb + OFF_X + (r * 3 + n - 253) * 4);
                                    uint16_t hh, ll; bf16_split(xv, hh, ll);
                                    uint32_t off = rbase + (((uint32_t)n * 2) ^ swr);
                                    sts_u16(sb + OFF_AH + off, hh);
                                    sts_u16(sb + OFF_AL + off, ll);
                                }
                            }
                        }
                    }
                }
        }

        if (dec) {
            #pragma unroll
            for (int mt = 0; mt < 4; ++mt)
                #pragma unroll
                for (int h = 0; h < 2; ++h) {
                    float s = dacc[mt][h];
                    s += __shfl_xor_sync(0xffffffffu, s, 1);
                    s += __shfl_xor_sync(0xffffffffu, s, 2);
                    if (qi == 0) {
                        int r = wm * 64 + mt * 16 + g + h * 8;
                        sts_f(sb + OFF_PS + r * 16 + wn * 4, s);
                    }
                }
            __syncthreads();
            if (tid < TILE_M) {
                float o = lds_f(sb + OFF_PS + tid * 16)
                        + lds_f(sb + OFF_PS + tid * 16 + 4)
                        + lds_f(sb + OFF_PS + tid * 16 + 8)
                        + lds_f(sb + OFF_PS + tid * 16 + 12);
                out[row0 + tid] = o + b2[0];
            }
        }
    }
}

// ---------------------------------------------------------------------------
extern "C" void kernel_launch(void* const* d_in, const int* in_sizes, int n_in,
                              void* d_out, int out_size) {
    const float* mu = (const float*)d_in[0];
    const float* x  = (const float*)d_in[1];
    const float* W1 = (const float*)d_in[2];
    const float* b1 = (const float*)d_in[3];
    const float* fw = (const float*)d_in[4];
    const float* lw = (const float*)d_in[5];
    const float* W2 = (const float*)d_in[6];
    const float* b2 = (const float*)d_in[7];
    float* out = (float*)d_out;

    const int B = in_sizes[0] / 64;

    build_mats<<<dim3(NL, 8), NM>>>(fw, lw);
    enc_split<<<64, 256>>>(W1);

    cudaFuncSetAttribute(fno_mma, cudaFuncAttributeMaxDynamicSharedMemorySize,
                         SMEM_TOTAL);
    fno_mma<<<B / TILE_M, 256, SMEM_TOTAL>>>(mu, x, b1, b2, W2, out);
}

// round 8
// speedup vs baseline: 3.5351x; 1.6084x over previous
#include <cuda_runtime.h>
#include <cuda_fp16.h>
#include <cstdint>

#define NM 256
#define NL 4
#define TILE_M 128

// Circulant tall tiles Btall[m][j] = c[(m-j-3)&255], fp16 hi/lo (exact pair).
__device__ __half g_Bc[NL][2][256][64];
__device__ __half g_W1[2][256][64];
__device__ float g_lwv[NL][NM];

// ---------------------------------------------------------------------------
__device__ __forceinline__ uint32_t smem_u32(const void* p) {
    uint32_t a;
    asm("{ .reg .u64 t; cvta.to.shared.u64 t, %1; cvt.u32.u64 %0, t; }"
        : "=r"(a) : "l"(p));
    return a;
}
__device__ __forceinline__ float lds_f(uint32_t a) {
    float v; asm volatile("ld.shared.f32 %0, [%1];" : "=f"(v) : "r"(a)); return v;
}
__device__ __forceinline__ uint32_t lds_u32(uint32_t a) {
    uint32_t v; asm volatile("ld.shared.b32 %0, [%1];" : "=r"(v) : "r"(a)); return v;
}
__device__ __forceinline__ uint16_t lds_u16(uint32_t a) {
    uint16_t v; asm volatile("ld.shared.u16 %0, [%1];" : "=h"(v) : "r"(a)); return v;
}
__device__ __forceinline__ void sts_f(uint32_t a, float v) {
    asm volatile("st.shared.f32 [%0], %1;" :: "r"(a), "f"(v) : "memory");
}
__device__ __forceinline__ void sts_u32(uint32_t a, uint32_t v) {
    asm volatile("st.shared.b32 [%0], %1;" :: "r"(a), "r"(v) : "memory");
}
__device__ __forceinline__ void sts_u16(uint32_t a, uint16_t v) {
    asm volatile("st.shared.b16 [%0], %1;" :: "r"(a), "h"(v) : "memory");
}
__device__ __forceinline__ void ldm_x4(uint32_t r[4], uint32_t addr) {
    asm volatile("ldmatrix.sync.aligned.m8n8.x4.shared.b16 {%0,%1,%2,%3}, [%4];"
                 : "=r"(r[0]), "=r"(r[1]), "=r"(r[2]), "=r"(r[3]) : "r"(addr));
}
__device__ __forceinline__ void mma16816(float c[4], const uint32_t a[4],
                                         uint32_t b0, uint32_t b1) {
    asm volatile("mma.sync.aligned.m16n8k16.row.col.f32.f16.f16.f32 "
                 "{%0,%1,%2,%3}, {%4,%5,%6,%7}, {%8,%9}, {%0,%1,%2,%3};"
                 : "+f"(c[0]), "+f"(c[1]), "+f"(c[2]), "+f"(c[3])
                 : "r"(a[0]), "r"(a[1]), "r"(a[2]), "r"(a[3]), "r"(b0), "r"(b1));
}
__device__ __forceinline__ void fp16_split(float v, uint16_t& h, uint16_t& l) {
    __half hb = __float2half_rn(v);
    __half lb = __float2half_rn(v - __half2float(hb));
    h = __half_as_ushort(hb);
    l = __half_as_ushort(lb);
}
__device__ __forceinline__ float hfu(uint16_t u) {
    return __half2float(__ushort_as_half(u));
}
#define CP_WAIT0() asm volatile("cp.async.wait_group 0;" ::: "memory")

// ---------------------------------------------------------------------------
__global__ void build_mats(const float* __restrict__ fw,
                           const float* __restrict__ lw) {
    const int l = blockIdx.x;
    const int kk = threadIdx.x;
    __shared__ float ks[NM];

    const float* fwl = fw + l * (NM / 2 + 1);
    float s = fwl[0];
    #pragma unroll 4
    for (int m = 1; m < NM / 2; ++m)
        s += 2.0f * fwl[m] * cospif((float)(m * kk) * (1.0f / 128.0f));
    s += fwl[NM / 2] * ((kk & 1) ? -1.0f : 1.0f);
    ks[kk] = s * (1.0f / 256.0f);
    if (blockIdx.y == 0) g_lwv[l][kk] = lw[l * NM + kk];
    __syncthreads();

    const int m0 = blockIdx.y * 32;
    for (int idx = kk; idx < 32 * 64; idx += 256) {
        int m = m0 + (idx >> 6), j = idx & 63;
        float v = ks[(m - j - 3) & (NM - 1)];
        uint16_t h, lo; fp16_split(v, h, lo);
        g_Bc[l][0][m][j] = __ushort_as_half(h);
        g_Bc[l][1][m][j] = __ushort_as_half(lo);
    }
}

__global__ void enc_split(const float* __restrict__ W1) {
    int i = blockIdx.x * 256 + threadIdx.x;
    int n = i >> 6, k = i & 63;
    float v = W1[k * NM + n];
    uint16_t h, lo; fp16_split(v, h, lo);
    g_W1[0][n][k] = __ushort_as_half(h);
    g_W1[1][n][k] = __ushort_as_half(lo);
}

// ---------------------------------------------------------------------------
// SMEM map (A is single fp16 buffer now)
// ---------------------------------------------------------------------------
#define A_ST 512
#define OFF_A  0u
#define OFF_B0 65536u
#define OFF_B1 98304u
#define OFF_LW 131072u
#define OFF_BB 132096u
#define OFF_W2 133120u
#define OFF_X  134144u
#define OFF_HS 136192u
#define OFF_PS 138240u
#define SMEM_TOTAL 140288

__device__ __forceinline__ void load_tile(const __half* g, uint32_t sbuf,
                                          int tid) {
    #pragma unroll
    for (int it = 0; it < 8; ++it) {
        int idx = it * 256 + tid;
        int row = idx >> 3, seg = idx & 7;
        const void* src = g + row * 64 + seg * 8;
        uint32_t dst = sbuf + row * 128 + ((seg * 16) ^ ((row & 7) * 16));
        asm volatile("cp.async.cg.shared.global [%0], [%1], 16;"
                     :: "r"(dst), "l"(src) : "memory");
    }
    asm volatile("cp.async.commit_group;" ::: "memory");
}

// ---------------------------------------------------------------------------
__global__ __launch_bounds__(256, 1)
void fno_mma(const float* __restrict__ mu, const float* __restrict__ x,
             const float* __restrict__ b1, const float* __restrict__ b2,
             const float* __restrict__ W2, float* __restrict__ out) {
    extern __shared__ __align__(16) unsigned char smraw[];
    const uint32_t sb = smem_u32(smraw);

    const int tid = threadIdx.x;
    const int lane = tid & 31, wid = tid >> 5;
    const int wm = wid >> 2, wn = wid & 3;
    const int g = lane >> 2, qi = lane & 3;
    const int r8 = lane & 7, q = lane >> 3;
    const long long row0 = (long long)blockIdx.x * TILE_M;

    const int rA0 = wm * 64 + r8 + (q & 1) * 8;
    const uint32_t swA = (uint32_t)(rA0 & 7) * 16;
    const int rB0 = wn * 64 + r8 + (q & 1) * 8;
    const uint32_t swB = (uint32_t)(rB0 & 7) * 16;
    const uint32_t cB16 = (uint32_t)(q >> 1) * 16;

    // kick encoder weight tiles
    load_tile(&g_W1[0][0][0], sb + OFF_B0, tid);
    load_tile(&g_W1[1][0][0], sb + OFF_B1, tid);

    // stage scalars
    sts_f(sb + OFF_BB + tid * 4, b1[tid]);
    sts_f(sb + OFF_W2 + tid * 4, W2[tid]);
    for (int i = tid; i < TILE_M * 3; i += 256) {
        int r = i / 3, c = i % 3;
        sts_f(sb + OFF_X + (r * 3 + c) * 4, x[(row0 + r) * 3 + c]);
    }
    // stage mu (cols 0-63 of A, fp16)
    {
        const float2* mu2 = (const float2*)(mu + row0 * 64);
        for (int i = tid; i < TILE_M * 32; i += 256) {
            int r = i >> 5, c2 = i & 31;
            float2 v = mu2[r * 32 + c2];
            uint16_t h0 = __half_as_ushort(__float2half_rn(v.x));
            uint16_t h1 = __half_as_ushort(__float2half_rn(v.y));
            uint32_t off = (uint32_t)r * A_ST + ((uint32_t)(c2 * 4) ^ ((r & 7) * 16));
            sts_u32(sb + OFF_A + off, (uint32_t)h0 | ((uint32_t)h1 << 16));
        }
    }

    float c[4][8][4];
    float dacc[4][2];

    for (int st = 0; st < 5; ++st) {
        const bool enc = (st == 0), dec = (st == 4);
        const int l = st - 1;

        CP_WAIT0();
        __syncthreads();
        if (!enc) sts_f(sb + OFF_LW + tid * 4, g_lwv[l][tid]);

        #pragma unroll
        for (int mt = 0; mt < 4; ++mt)
            #pragma unroll
            for (int nt = 0; nt < 8; ++nt)
                #pragma unroll
                for (int e = 0; e < 4; ++e) c[mt][nt][e] = 0.f;
        if (dec) {
            #pragma unroll
            for (int mt = 0; mt < 4; ++mt) dacc[mt][0] = dacc[mt][1] = 0.f;
        }

        const int ns = enc ? 1 : 4;
        for (int s = 0; s < ns; ++s) {
            const int rBs = (rB0 - 64 * s) & 255;
            const uint32_t aCol0 = (uint32_t)s * 128 + cB16;
            #pragma unroll
            for (int kc = 0; kc < 4; ++kc) {
                const uint32_t aCsw = ((aCol0 + kc * 32) ^ swA);
                const uint32_t bCsw = (((uint32_t)kc * 32 + cB16) ^ swB);
                uint32_t aF[4][4], b0f[4][4], b1f[4][4];
                #pragma unroll
                for (int mt = 0; mt < 4; ++mt)
                    ldm_x4(aF[mt], sb + OFF_A + (uint32_t)(rA0 + mt * 16) * A_ST + aCsw);
                #pragma unroll
                for (int np = 0; np < 4; ++np) {
                    uint32_t ro = (uint32_t)(((rBs + np * 16) & 255)) * 128;
                    ldm_x4(b0f[np], sb + OFF_B0 + ro + bCsw);
                    ldm_x4(b1f[np], sb + OFF_B1 + ro + bCsw);
                }
                #pragma unroll
                for (int mt = 0; mt < 4; ++mt)
                    #pragma unroll
                    for (int np = 0; np < 4; ++np) {
                        mma16816(c[mt][2 * np],     aF[mt], b0f[np][0], b0f[np][2]);
                        mma16816(c[mt][2 * np + 1], aF[mt], b0f[np][1], b0f[np][3]);
                        mma16816(c[mt][2 * np],     aF[mt], b1f[np][0], b1f[np][2]);
                        mma16816(c[mt][2 * np + 1], aF[mt], b1f[np][1], b1f[np][3]);
                    }
            }
        }
        __syncthreads();

        if (st < 4) {   // prefetch next layer's circulant tiles
            load_tile(&g_Bc[st][0][0][0], sb + OFF_B0, tid);
            load_tile(&g_Bc[st][1][0][0], sb + OFF_B1, tid);
        }

        // -------- epilogue (each (r,n) owned by one thread) --------
        #pragma unroll
        for (int nt = 0; nt < 8; ++nt) {
            const int c0 = wn * 64 + nt * 8 + qi * 2;
            float lw0 = 0.f, lw1 = 0.f, bb0 = 0.f, bb1 = 0.f, w0 = 0.f, w1 = 0.f;
            if (enc) {
                bb0 = lds_f(sb + OFF_BB + c0 * 4);
                bb1 = lds_f(sb + OFF_BB + c0 * 4 + 4);
            } else {
                lw0 = lds_f(sb + OFF_LW + c0 * 4);
                lw1 = lds_f(sb + OFF_LW + c0 * 4 + 4);
            }
            if (dec) {
                w0 = lds_f(sb + OFF_W2 + c0 * 4);
                w1 = lds_f(sb + OFF_W2 + c0 * 4 + 4);
            }
            #pragma unroll
            for (int mt = 0; mt < 4; ++mt)
                #pragma unroll
                for (int h = 0; h < 2; ++h) {
                    const int r = wm * 64 + mt * 16 + g + h * 8;
                    const uint32_t swr = (uint32_t)(r & 7) * 16;
                    const uint32_t rbase = (uint32_t)r * A_ST;
                    float v0 = c[mt][nt][2 * h], v1 = c[mt][nt][2 * h + 1];

                    if (enc) {
                        v0 += bb0; v1 += bb1;
                    } else {
                        float hp0, hp1;
                        if (c0 < 252) {
                            uint32_t uh = lds_u32(sb + OFF_A + rbase + (((uint32_t)c0 * 2) ^ swr));
                            hp0 = hfu((uint16_t)uh);
                            hp1 = hfu((uint16_t)(uh >> 16));
                        } else {
                            hp0 = (c0 < 253)
                                ? hfu(lds_u16(sb + OFF_A + rbase + (((uint32_t)c0 * 2) ^ swr)))
                                : lds_f(sb + OFF_HS + (r * 3 + c0 - 253) * 4);
                            hp1 = (c0 + 1 < 253)
                                ? 0.f
                                : lds_f(sb + OFF_HS + (r * 3 + c0 + 1 - 253) * 4);
                        }
                        v0 += lw0 * hp0; v1 += lw1 * hp1;
                    }
                    v0 = fmaxf(v0, 0.f); v1 = fmaxf(v1, 0.f);

                    if (dec) {
                        dacc[mt][h] += v0 * w0 + v1 * w1;
                    } else if (c0 < 252) {
                        uint16_t h0 = __half_as_ushort(__float2half_rn(v0));
                        uint16_t h1 = __half_as_ushort(__float2half_rn(v1));
                        uint32_t off = rbase + (((uint32_t)c0 * 2) ^ swr);
                        sts_u32(sb + OFF_A + off, (uint32_t)h0 | ((uint32_t)h1 << 16));
                    } else {
                        #pragma unroll
                        for (int e = 0; e < 2; ++e) {
                            int n = c0 + e;
                            float v = e ? v1 : v0;
                            if (n < 253) {
                                uint32_t off = rbase + (((uint32_t)n * 2) ^ swr);
                                sts_u16(sb + OFF_A + off,
                                        __half_as_ushort(__float2half_rn(v)));
                            } else {
                                sts_f(sb + OFF_HS + (r * 3 + n - 253) * 4, v);
                                if (enc) {
                                    float xv = lds_f(sb + OFF_X + (r * 3 + n - 253) * 4);
                                    uint32_t off = rbase + (((uint32_t)n * 2) ^ swr);
                                    sts_u16(sb + OFF_A + off,
                                            __half_as_ushort(__float2half_rn(xv)));
                                }
                            }
                        }
                    }
                }
        }

        if (dec) {
            #pragma unroll
            for (int mt = 0; mt < 4; ++mt)
                #pragma unroll
                for (int h = 0; h < 2; ++h) {
                    float s = dacc[mt][h];
                    s += __shfl_xor_sync(0xffffffffu, s, 1);
                    s += __shfl_xor_sync(0xffffffffu, s, 2);
                    if (qi == 0) {
                        int r = wm * 64 + mt * 16 + g + h * 8;
                        sts_f(sb + OFF_PS + r * 16 + wn * 4, s);
                    }
                }
            __syncthreads();
            if (tid < TILE_M) {
                float o = lds_f(sb + OFF_PS + tid * 16)
                        + lds_f(sb + OFF_PS + tid * 16 + 4)
                        + lds_f(sb + OFF_PS + tid * 16 + 8)
                        + lds_f(sb + OFF_PS + tid * 16 + 12);
                out[row0 + tid] = o + b2[0];
            }
        }
    }
}

// ---------------------------------------------------------------------------
extern "C" void kernel_launch(void* const* d_in, const int* in_sizes, int n_in,
                              void* d_out, int out_size) {
    const float* mu = (const float*)d_in[0];
    const float* x  = (const float*)d_in[1];
    const float* W1 = (const float*)d_in[2];
    const float* b1 = (const float*)d_in[3];
    const float* fw = (const float*)d_in[4];
    const float* lw = (const float*)d_in[5];
    const float* W2 = (const float*)d_in[6];
    const float* b2 = (const float*)d_in[7];
    float* out = (float*)d_out;

    const int B = in_sizes[0] / 64;

    build_mats<<<dim3(NL, 8), NM>>>(fw, lw);
    enc_split<<<64, 256>>>(W1);

    cudaFuncSetAttribute(fno_mma, cudaFuncAttributeMaxDynamicSharedMemorySize,
                         SMEM_TOTAL);
    fno_mma<<<B / TILE_M, 256, SMEM_TOTAL>>>(mu, x, b1, b2, W2, out);
}

// round 9
// speedup vs baseline: 3.8644x; 1.0932x over previous
#include <cuda_runtime.h>
#include <cuda_fp16.h>
#include <cstdint>

#define NM 256
#define NL 4
#define TILE_M 128
#define NTHREADS 512

// Circulant tall tiles Btall[m][j] = c[(m-j-3)&255], fp16 hi/lo (exact pair).
__device__ __half g_Bc[NL][2][256][64];
__device__ __half g_W1[2][256][64];
__device__ float g_lwv[NL][NM];

// ---------------------------------------------------------------------------
__device__ __forceinline__ uint32_t smem_u32(const void* p) {
    uint32_t a;
    asm("{ .reg .u64 t; cvta.to.shared.u64 t, %1; cvt.u32.u64 %0, t; }"
        : "=r"(a) : "l"(p));
    return a;
}
__device__ __forceinline__ float lds_f(uint32_t a) {
    float v; asm volatile("ld.shared.f32 %0, [%1];" : "=f"(v) : "r"(a)); return v;
}
__device__ __forceinline__ uint32_t lds_u32(uint32_t a) {
    uint32_t v; asm volatile("ld.shared.b32 %0, [%1];" : "=r"(v) : "r"(a)); return v;
}
__device__ __forceinline__ uint16_t lds_u16(uint32_t a) {
    uint16_t v; asm volatile("ld.shared.u16 %0, [%1];" : "=h"(v) : "r"(a)); return v;
}
__device__ __forceinline__ void sts_f(uint32_t a, float v) {
    asm volatile("st.shared.f32 [%0], %1;" :: "r"(a), "f"(v) : "memory");
}
__device__ __forceinline__ void sts_u32(uint32_t a, uint32_t v) {
    asm volatile("st.shared.b32 [%0], %1;" :: "r"(a), "r"(v) : "memory");
}
__device__ __forceinline__ void sts_u16(uint32_t a, uint16_t v) {
    asm volatile("st.shared.b16 [%0], %1;" :: "r"(a), "h"(v) : "memory");
}
__device__ __forceinline__ void ldm_x4(uint32_t r[4], uint32_t addr) {
    asm volatile("ldmatrix.sync.aligned.m8n8.x4.shared.b16 {%0,%1,%2,%3}, [%4];"
                 : "=r"(r[0]), "=r"(r[1]), "=r"(r[2]), "=r"(r[3]) : "r"(addr));
}
__device__ __forceinline__ void mma16816(float c[4], const uint32_t a[4],
                                         uint32_t b0, uint32_t b1) {
    asm volatile("mma.sync.aligned.m16n8k16.row.col.f32.f16.f16.f32 "
                 "{%0,%1,%2,%3}, {%4,%5,%6,%7}, {%8,%9}, {%0,%1,%2,%3};"
                 : "+f"(c[0]), "+f"(c[1]), "+f"(c[2]), "+f"(c[3])
                 : "r"(a[0]), "r"(a[1]), "r"(a[2]), "r"(a[3]), "r"(b0), "r"(b1));
}
__device__ __forceinline__ void fp16_split(float v, uint16_t& h, uint16_t& l) {
    __half hb = __float2half_rn(v);
    __half lb = __float2half_rn(v - __half2float(hb));
    h = __half_as_ushort(hb);
    l = __half_as_ushort(lb);
}
__device__ __forceinline__ float hfu(uint16_t u) {
    return __half2float(__ushort_as_half(u));
}
#define CP_WAIT0() asm volatile("cp.async.wait_group 0;" ::: "memory")

// ---------------------------------------------------------------------------
__global__ void build_mats(const float* __restrict__ fw,
                           const float* __restrict__ lw) {
    const int l = blockIdx.x;
    const int kk = threadIdx.x;
    __shared__ float ks[NM];

    const float* fwl = fw + l * (NM / 2 + 1);
    float s = fwl[0];
    #pragma unroll 4
    for (int m = 1; m < NM / 2; ++m)
        s += 2.0f * fwl[m] * cospif((float)(m * kk) * (1.0f / 128.0f));
    s += fwl[NM / 2] * ((kk & 1) ? -1.0f : 1.0f);
    ks[kk] = s * (1.0f / 256.0f);
    if (blockIdx.y == 0) g_lwv[l][kk] = lw[l * NM + kk];
    __syncthreads();

    const int m0 = blockIdx.y * 32;
    for (int idx = kk; idx < 32 * 64; idx += 256) {
        int m = m0 + (idx >> 6), j = idx & 63;
        float v = ks[(m - j - 3) & (NM - 1)];
        uint16_t h, lo; fp16_split(v, h, lo);
        g_Bc[l][0][m][j] = __ushort_as_half(h);
        g_Bc[l][1][m][j] = __ushort_as_half(lo);
    }
}

__global__ void enc_split(const float* __restrict__ W1) {
    int i = blockIdx.x * 256 + threadIdx.x;
    int n = i >> 6, k = i & 63;
    float v = W1[k * NM + n];
    uint16_t h, lo; fp16_split(v, h, lo);
    g_W1[0][n][k] = __ushort_as_half(h);
    g_W1[1][n][k] = __ushort_as_half(lo);
}

// ---------------------------------------------------------------------------
#define A_ST 512
#define OFF_A  0u
#define OFF_B0 65536u
#define OFF_B1 98304u
#define OFF_LW 131072u
#define OFF_BB 132096u
#define OFF_W2 133120u
#define OFF_X  134144u
#define OFF_HS 136192u
#define OFF_PS 138240u
#define SMEM_TOTAL 140288

__device__ __forceinline__ void load_tile(const __half* g, uint32_t sbuf,
                                          int tid) {
    #pragma unroll
    for (int it = 0; it < 4; ++it) {
        int idx = it * NTHREADS + tid;
        int row = idx >> 3, seg = idx & 7;
        const void* src = g + row * 64 + seg * 8;
        uint32_t dst = sbuf + row * 128 + ((seg * 16) ^ ((row & 7) * 16));
        asm volatile("cp.async.cg.shared.global [%0], [%1], 16;"
                     :: "r"(dst), "l"(src) : "memory");
    }
    asm volatile("cp.async.commit_group;" ::: "memory");
}

// ---------------------------------------------------------------------------
__global__ __launch_bounds__(NTHREADS, 1)
void fno_mma(const float* __restrict__ mu, const float* __restrict__ x,
             const float* __restrict__ b1, const float* __restrict__ b2,
             const float* __restrict__ W2, float* __restrict__ out) {
    extern __shared__ __align__(16) unsigned char smraw[];
    const uint32_t sb = smem_u32(smraw);

    const int tid = threadIdx.x;
    const int lane = tid & 31, wid = tid >> 5;
    const int wm = wid >> 2, wn = wid & 3;       // 4x4 warp grid, 32x64 tiles
    const int g = lane >> 2, qi = lane & 3;
    const int r8 = lane & 7, q = lane >> 3;
    const long long row0 = (long long)blockIdx.x * TILE_M;

    const int rA0 = wm * 32 + r8 + (q & 1) * 8;
    const uint32_t swA = (uint32_t)(rA0 & 7) * 16;
    const int rB0 = wn * 64 + r8 + (q & 1) * 8;
    const uint32_t swB = (uint32_t)(rB0 & 7) * 16;
    const uint32_t cB16 = (uint32_t)(q >> 1) * 16;

    // kick encoder weight tiles
    load_tile(&g_W1[0][0][0], sb + OFF_B0, tid);
    load_tile(&g_W1[1][0][0], sb + OFF_B1, tid);

    // stage scalars
    if (tid < 256) {
        sts_f(sb + OFF_BB + tid * 4, b1[tid]);
        sts_f(sb + OFF_W2 + tid * 4, W2[tid]);
    }
    for (int i = tid; i < TILE_M * 3; i += NTHREADS) {
        int r = i / 3, c = i % 3;
        sts_f(sb + OFF_X + (r * 3 + c) * 4, x[(row0 + r) * 3 + c]);
    }
    // stage mu (cols 0-63 of A, fp16)
    {
        const float2* mu2 = (const float2*)(mu + row0 * 64);
        for (int i = tid; i < TILE_M * 32; i += NTHREADS) {
            int r = i >> 5, c2 = i & 31;
            float2 v = mu2[r * 32 + c2];
            uint16_t h0 = __half_as_ushort(__float2half_rn(v.x));
            uint16_t h1 = __half_as_ushort(__float2half_rn(v.y));
            uint32_t off = (uint32_t)r * A_ST + ((uint32_t)(c2 * 4) ^ ((r & 7) * 16));
            sts_u32(sb + OFF_A + off, (uint32_t)h0 | ((uint32_t)h1 << 16));
        }
    }

    float c[2][8][4];
    float dacc[2][2];

    for (int st = 0; st < 5; ++st) {
        const bool enc = (st == 0), dec = (st == 4);
        const int l = st - 1;

        CP_WAIT0();
        __syncthreads();
        if (!enc && tid < 256) sts_f(sb + OFF_LW + tid * 4, g_lwv[l][tid]);

        #pragma unroll
        for (int mt = 0; mt < 2; ++mt)
            #pragma unroll
            for (int nt = 0; nt < 8; ++nt)
                #pragma unroll
                for (int e = 0; e < 4; ++e) c[mt][nt][e] = 0.f;
        if (dec) {
            #pragma unroll
            for (int mt = 0; mt < 2; ++mt) dacc[mt][0] = dacc[mt][1] = 0.f;
        }

        const int ns = enc ? 1 : 4;
        for (int s = 0; s < ns; ++s) {
            const int rBs = (rB0 - 64 * s) & 255;
            const uint32_t aCol0 = (uint32_t)s * 128 + cB16;
            #pragma unroll
            for (int kc = 0; kc < 4; ++kc) {
                const uint32_t aCsw = ((aCol0 + kc * 32) ^ swA);
                const uint32_t bCsw = (((uint32_t)kc * 32 + cB16) ^ swB);
                uint32_t aF[2][4], b0f[4][4], b1f[4][4];
                #pragma unroll
                for (int mt = 0; mt < 2; ++mt)
                    ldm_x4(aF[mt], sb + OFF_A + (uint32_t)(rA0 + mt * 16) * A_ST + aCsw);
                #pragma unroll
                for (int np = 0; np < 4; ++np) {
                    uint32_t ro = (uint32_t)(((rBs + np * 16) & 255)) * 128;
                    ldm_x4(b0f[np], sb + OFF_B0 + ro + bCsw);
                    ldm_x4(b1f[np], sb + OFF_B1 + ro + bCsw);
                }
                #pragma unroll
                for (int mt = 0; mt < 2; ++mt)
                    #pragma unroll
                    for (int np = 0; np < 4; ++np) {
                        mma16816(c[mt][2 * np],     aF[mt], b0f[np][0], b0f[np][2]);
                        mma16816(c[mt][2 * np + 1], aF[mt], b0f[np][1], b0f[np][3]);
                        mma16816(c[mt][2 * np],     aF[mt], b1f[np][0], b1f[np][2]);
                        mma16816(c[mt][2 * np + 1], aF[mt], b1f[np][1], b1f[np][3]);
                    }
            }
        }
        __syncthreads();

        if (st < 4) {   // prefetch next layer's circulant tiles
            load_tile(&g_Bc[st][0][0][0], sb + OFF_B0, tid);
            load_tile(&g_Bc[st][1][0][0], sb + OFF_B1, tid);
        }

        // -------- epilogue (each (r,n) owned by one thread) --------
        #pragma unroll
        for (int nt = 0; nt < 8; ++nt) {
            const int c0 = wn * 64 + nt * 8 + qi * 2;
            float lw0 = 0.f, lw1 = 0.f, bb0 = 0.f, bb1 = 0.f, w0 = 0.f, w1 = 0.f;
            if (enc) {
                bb0 = lds_f(sb + OFF_BB + c0 * 4);
                bb1 = lds_f(sb + OFF_BB + c0 * 4 + 4);
            } else {
                lw0 = lds_f(sb + OFF_LW + c0 * 4);
                lw1 = lds_f(sb + OFF_LW + c0 * 4 + 4);
            }
            if (dec) {
                w0 = lds_f(sb + OFF_W2 + c0 * 4);
                w1 = lds_f(sb + OFF_W2 + c0 * 4 + 4);
            }
            #pragma unroll
            for (int mt = 0; mt < 2; ++mt)
                #pragma unroll
                for (int h = 0; h < 2; ++h) {
                    const int r = wm * 32 + mt * 16 + g + h * 8;
                    const uint32_t swr = (uint32_t)(r & 7) * 16;
                    const uint32_t rbase = (uint32_t)r * A_ST;
                    float v0 = c[mt][nt][2 * h], v1 = c[mt][nt][2 * h + 1];

                    if (enc) {
                        v0 += bb0; v1 += bb1;
                    } else {
                        float hp0, hp1;
                        if (c0 < 252) {
                            uint32_t uh = lds_u32(sb + OFF_A + rbase + (((uint32_t)c0 * 2) ^ swr));
                            hp0 = hfu((uint16_t)uh);
                            hp1 = hfu((uint16_t)(uh >> 16));
                        } else {
                            hp0 = (c0 < 253)
                                ? hfu(lds_u16(sb + OFF_A + rbase + (((uint32_t)c0 * 2) ^ swr)))
                                : lds_f(sb + OFF_HS + (r * 3 + c0 - 253) * 4);
                            hp1 = (c0 + 1 < 253)
                                ? 0.f
                                : lds_f(sb + OFF_HS + (r * 3 + c0 + 1 - 253) * 4);
                        }
                        v0 += lw0 * hp0; v1 += lw1 * hp1;
                    }
                    v0 = fmaxf(v0, 0.f); v1 = fmaxf(v1, 0.f);

                    if (dec) {
                        dacc[mt][h] += v0 * w0 + v1 * w1;
                    } else if (c0 < 252) {
                        uint16_t h0 = __half_as_ushort(__float2half_rn(v0));
                        uint16_t h1 = __half_as_ushort(__float2half_rn(v1));
                        uint32_t off = rbase + (((uint32_t)c0 * 2) ^ swr);
                        sts_u32(sb + OFF_A + off, (uint32_t)h0 | ((uint32_t)h1 << 16));
                    } else {
                        #pragma unroll
                        for (int e = 0; e < 2; ++e) {
                            int n = c0 + e;
                            float v = e ? v1 : v0;
                            if (n < 253) {
                                uint32_t off = rbase + (((uint32_t)n * 2) ^ swr);
                                sts_u16(sb + OFF_A + off,
                                        __half_as_ushort(__float2half_rn(v)));
                            } else {
                                sts_f(sb + OFF_HS + (r * 3 + n - 253) * 4, v);
                                if (enc) {
                                    float xv = lds_f(sb + OFF_X + (r * 3 + n - 253) * 4);
                                    uint32_t off = rbase + (((uint32_t)n * 2) ^ swr);
                                    sts_u16(sb + OFF_A + off,
                                            __half_as_ushort(__float2half_rn(xv)));
                                }
                            }
                        }
                    }
                }
        }

        if (dec) {
            #pragma unroll
            for (int mt = 0; mt < 2; ++mt)
                #pragma unroll
                for (int h = 0; h < 2; ++h) {
                    float s = dacc[mt][h];
                    s += __shfl_xor_sync(0xffffffffu, s, 1);
                    s += __shfl_xor_sync(0xffffffffu, s, 2);
                    if (qi == 0) {
                        int r = wm * 32 + mt * 16 + g + h * 8;
                        sts_f(sb + OFF_PS + r * 16 + wn * 4, s);
                    }
                }
            __syncthreads();
            if (tid < TILE_M) {
                float o = lds_f(sb + OFF_PS + tid * 16)
                        + lds_f(sb + OFF_PS + tid * 16 + 4)
                        + lds_f(sb + OFF_PS + tid * 16 + 8)
                        + lds_f(sb + OFF_PS + tid * 16 + 12);
                out[row0 + tid] = o + b2[0];
            }
        }
    }
}

// ---------------------------------------------------------------------------
extern "C" void kernel_launch(void* const* d_in, const int* in_sizes, int n_in,
                              void* d_out, int out_size) {
    const float* mu = (const float*)d_in[0];
    const float* x  = (const float*)d_in[1];
    const float* W1 = (const float*)d_in[2];
    const float* b1 = (const float*)d_in[3];
    const float* fw = (const float*)d_in[4];
    const float* lw = (const float*)d_in[5];
    const float* W2 = (const float*)d_in[6];
    const float* b2 = (const float*)d_in[7];
    float* out = (float*)d_out;

    const int B = in_sizes[0] / 64;

    build_mats<<<dim3(NL, 8), NM>>>(fw, lw);
    enc_split<<<64, 256>>>(W1);

    cudaFuncSetAttribute(fno_mma, cudaFuncAttributeMaxDynamicSharedMemorySize,
                         SMEM_TOTAL);
    fno_mma<<<B / TILE_M, NTHREADS, SMEM_TOTAL>>>(mu, x, b1, b2, W2, out);
}